// round 2
// baseline (speedup 1.0000x reference)
#include <cuda_runtime.h>

#define NN 4096
#define INF 256
#define OF 64
#define NH 4

// Scratch (static device globals — no allocation in kernel_launch)
__device__ float    g_xt[NH][NN][OF];      // per-head transformed features
__device__ float4   g_idat[NH][NN];        // {src, exp(src), exp(0.2*src), 0}
__device__ float4   g_jdat[NH][NN];        // {dst, exp(dst), exp(0.2*dst), 0}
__device__ unsigned g_adjT[NN / 32][NN];   // adjacency bits, [wordcol][row] (transposed for coalesced loads)

typedef unsigned long long ull;

__device__ __forceinline__ ull dup2(float v) {
    ull r;
    asm("mov.b64 %0, {%1, %1};" : "=l"(r) : "f"(v));
    return r;
}
__device__ __forceinline__ void fma2(ull& d, ull a, ull b) {
    asm("fma.rn.f32x2 %0, %1, %2, %0;" : "+l"(d) : "l"(a), "l"(b));
}
__device__ __forceinline__ float2 unpack2(ull v) {
    float2 r;
    asm("mov.b64 {%0, %1}, %2;" : "=f"(r.x), "=f"(r.y) : "l"(v));
    return r;
}

// ---------------------------------------------------------------------------
// Kernel 1: pack adjacency into transposed bitmask g_adjT[wordcol][row]
// ---------------------------------------------------------------------------
__global__ void k_bitpack(const int* __restrict__ adj) {
    int gw   = (blockIdx.x * 256 + threadIdx.x) >> 5;  // global warp id
    int lane = threadIdx.x & 31;
    int row  = gw >> 7;        // 0..4095
    int wc   = gw & 127;       // 0..127
    unsigned m = __ballot_sync(0xffffffffu, adj[row * NN + wc * 32 + lane] > 0);
    if (lane == 0) g_adjT[wc][row] = m;
}

// ---------------------------------------------------------------------------
// Kernel 2: xt[h][n][f] = x[n,:] @ W[h,:,f]   (M=4096, K=256, per-head N=64)
// Block: 256 threads, 64x64 tile, 4x4 microtile, K-step 16.
// ---------------------------------------------------------------------------
__global__ __launch_bounds__(256) void k_xt(const float* __restrict__ x,
                                            const float* __restrict__ W) {
    __shared__ float sx[16][68];   // x^T chunk: sx[k][n]
    __shared__ float sw[16][64];   // W  chunk: sw[k][f]
    const int h  = blockIdx.y;
    const int n0 = blockIdx.x * 64;
    const int t  = threadIdx.x;
    const int tx = t & 15, ty = t >> 4;
    const float* Wh = W + h * INF * OF;

    float acc[4][4] = {};
    for (int k0 = 0; k0 < INF; k0 += 16) {
        // stage loads into registers first
        const int n  = t >> 2, kq = (t & 3) * 4;
        float4 xv = *(const float4*)(x + (n0 + n) * INF + k0 + kq);
        const int kk = t & 15, f4 = t >> 4;
        float4 wv = *(const float4*)(Wh + (kk + k0) * OF + f4 * 4);
        __syncthreads();   // previous compute done reading smem
        sx[kq + 0][n] = xv.x; sx[kq + 1][n] = xv.y;
        sx[kq + 2][n] = xv.z; sx[kq + 3][n] = xv.w;
        *(float4*)&sw[kk][f4 * 4] = wv;
        __syncthreads();
        #pragma unroll
        for (int k = 0; k < 16; k++) {
            float4 av = *(float4*)&sx[k][ty * 4];
            float4 bv = *(float4*)&sw[k][tx * 4];
            acc[0][0] += av.x * bv.x; acc[0][1] += av.x * bv.y; acc[0][2] += av.x * bv.z; acc[0][3] += av.x * bv.w;
            acc[1][0] += av.y * bv.x; acc[1][1] += av.y * bv.y; acc[1][2] += av.y * bv.z; acc[1][3] += av.y * bv.w;
            acc[2][0] += av.z * bv.x; acc[2][1] += av.z * bv.y; acc[2][2] += av.z * bv.z; acc[2][3] += av.z * bv.w;
            acc[3][0] += av.w * bv.x; acc[3][1] += av.w * bv.y; acc[3][2] += av.w * bv.z; acc[3][3] += av.w * bv.w;
        }
    }
    #pragma unroll
    for (int r = 0; r < 4; r++) {
        float4 o = make_float4(acc[r][0], acc[r][1], acc[r][2], acc[r][3]);
        *(float4*)&g_xt[h][n0 + ty * 4 + r][tx * 4] = o;
    }
}

// ---------------------------------------------------------------------------
// Kernel 3: per-(h,n) scalars: src/dst dot products -> exp tables
// One warp per (h,n); lane covers features {lane, lane+32}.
// ---------------------------------------------------------------------------
__global__ void k_rowdat(const float* __restrict__ a) {
    int gid  = (blockIdx.x * 256 + threadIdx.x) >> 5;
    int lane = threadIdx.x & 31;
    int h = gid >> 12, n = gid & (NN - 1);
    const float* xr = g_xt[h][n];
    const float* ah = a + h * 2 * OF;
    float v0 = xr[lane], v1 = xr[lane + 32];
    float src = v0 * ah[lane]      + v1 * ah[lane + 32];
    float dst = v0 * ah[64 + lane] + v1 * ah[96 + lane];
    #pragma unroll
    for (int s = 16; s; s >>= 1) {
        src += __shfl_xor_sync(0xffffffffu, src, s);
        dst += __shfl_xor_sync(0xffffffffu, dst, s);
    }
    if (lane == 0) {
        g_idat[h][n] = make_float4(src, expf(src), expf(0.2f * src), 0.f);
        g_jdat[h][n] = make_float4(dst, expf(dst), expf(0.2f * dst), 0.f);
    }
}

// ---------------------------------------------------------------------------
// Kernel 4 (main): per block = (head h, 64 i-rows). Loop over 64-wide j tiles:
//   stage A: build w[j][i] tile in smem (compare+select, no exp) + Z partials
//   stage B: acc[i][f] += w @ xt  via packed fma.rn.f32x2
// Epilogue: out = acc / Z
// ---------------------------------------------------------------------------
__global__ __launch_bounds__(256, 2) void k_main(float* __restrict__ out) {
    __shared__ float  ws[64][68];    // k(=j)-major weight tile, padded stride
    __shared__ float4 xts[64][16];   // xt tile: [k][f4]
    __shared__ float  zred[4][64];
    __shared__ float  zinv[64];

    const int h  = blockIdx.y;
    const int i0 = blockIdx.x * 64;
    const int t  = threadIdx.x;

    // stage-A identity: fixed i-row per thread, 16-wide j strip
    const int il = t & 63, jstrip = t >> 6;
    const float4 idat = g_idat[h][i0 + il];
    const float si = idat.x, A1 = idat.y, A2 = idat.z;
    float zacc = 0.f;

    // stage-B identity: 4 rows x 4 cols microtile
    const int tx = t & 15, ty = t >> 4;
    ull acc[4][2];
    #pragma unroll
    for (int r = 0; r < 4; r++) { acc[r][0] = 0ULL; acc[r][1] = 0ULL; }

    for (int jt = 0; jt < 64; jt++) {
        const int j0 = jt * 64;
        __syncthreads();  // previous stage B finished reading ws/xts

        // cooperative xt tile load (coalesced float4)
        #pragma unroll
        for (int e = 0; e < 4; e++) {
            int lin = t + e * 256;
            int k = lin >> 4, f4 = lin & 15;
            xts[k][f4] = *(const float4*)&g_xt[h][j0 + k][f4 * 4];
        }

        // stage A: adjacency bits (coalesced via transposed layout) + weights
        unsigned word = g_adjT[(j0 >> 5) + (jstrip >> 1)][i0 + il];
        unsigned bits = word >> ((jstrip & 1) * 16);
        #pragma unroll
        for (int e = 0; e < 16; e++) {
            int jl = jstrip * 16 + e;
            float4 jd = g_jdat[h][j0 + jl];             // warp-uniform L1 hit
            float c = si + jd.x;
            float w = (c >= 0.f) ? (A1 * jd.y) : (A2 * jd.z);
            w = ((bits >> e) & 1u) ? w : 0.f;
            zacc += w;
            ws[jl][il] = w;                             // conflict-free: il contiguous
        }
        __syncthreads();

        // stage B: 64x64x64 fp32 GEMM slab with packed f32x2 FMA
        #pragma unroll 4
        for (int k = 0; k < 64; k++) {
            float4 bv = xts[k][tx];
            ull b01, b23;
            asm("mov.b64 %0, {%1, %2};" : "=l"(b01) : "f"(bv.x), "f"(bv.y));
            asm("mov.b64 %0, {%1, %2};" : "=l"(b23) : "f"(bv.z), "f"(bv.w));
            float4 av = *(float4*)&ws[k][ty * 4];
            ull w0 = dup2(av.x), w1 = dup2(av.y), w2 = dup2(av.z), w3 = dup2(av.w);
            fma2(acc[0][0], w0, b01); fma2(acc[0][1], w0, b23);
            fma2(acc[1][0], w1, b01); fma2(acc[1][1], w1, b23);
            fma2(acc[2][0], w2, b01); fma2(acc[2][1], w2, b23);
            fma2(acc[3][0], w3, b01); fma2(acc[3][1], w3, b23);
        }
    }

    // reduce Z across the 4 j-strip threads per row
    zred[jstrip][il] = zacc;
    __syncthreads();
    if (t < 64) {
        float z = zred[0][t] + zred[1][t] + zred[2][t] + zred[3][t];
        zinv[t] = 1.0f / z;
    }
    __syncthreads();

    // epilogue: normalize and write out[n][h*64+f]
    #pragma unroll
    for (int r = 0; r < 4; r++) {
        int i = ty * 4 + r;
        float zi = zinv[i];
        float2 p0 = unpack2(acc[r][0]);
        float2 p1 = unpack2(acc[r][1]);
        float4 o = make_float4(p0.x * zi, p0.y * zi, p1.x * zi, p1.y * zi);
        *(float4*)&out[(i0 + i) * (NH * OF) + h * OF + tx * 4] = o;
    }
}

// ---------------------------------------------------------------------------
extern "C" void kernel_launch(void* const* d_in, const int* in_sizes, int n_in,
                              void* d_out, int out_size) {
    const float* x   = (const float*)d_in[0];  // [4096, 256]
    const float* W   = (const float*)d_in[1];  // [4, 256, 64]
    const float* a   = (const float*)d_in[2];  // [4, 128]
    const int*   adj = (const int*)d_in[3];    // [4096, 4096]
    float* out = (float*)d_out;                // [4096, 256]

    (void)in_sizes; (void)n_in; (void)out_size;

    k_bitpack<<<(NN * (NN / 32)) / 8, 256>>>(adj);
    k_xt<<<dim3(NN / 64, NH), 256>>>(x, W);
    k_rowdat<<<(NH * NN) / 8, 256>>>(a);
    k_main<<<dim3(NN / 64, NH), 256>>>(out);
}

// round 4
// speedup vs baseline: 1.5068x; 1.5068x over previous
#include <cuda_runtime.h>
#include <cuda_bf16.h>
#include <cstdint>

#define NN 4096
#define INF 256
#define OF 64
#define NH 4

// ---------------------------------------------------------------------------
// Scratch globals
// ---------------------------------------------------------------------------
__device__ float    g_xt[NH][NN][OF];      // per-head transformed features
__device__ float4   g_idat[NH][NN];        // {src, exp(src), exp(0.2*src), 0}
__device__ float4   g_jdat[NH][NN];        // {dst, exp(dst), exp(0.2*dst), 0}
__device__ unsigned g_adjT[NN / 32][NN];   // adjacency bits [wordcol][row]
// V tiles: per (h,chunk): 4 segs (V1hi,V1lo,V2hi,V2lo), each [64 k][72 n] bf16,
// row stride 144B (ldmatrix conflict-free). col 64 = E value, cols 65..71 = 0.
#define SEGB 9216
#define VCH  (4 * SEGB)
__device__ __align__(16) char g_Vt[NH * 64 * VCH];

// ---------------------------------------------------------------------------
// PTX helpers (family-generic only: no tcgen05 on this target)
// ---------------------------------------------------------------------------
__device__ __forceinline__ uint32_t smem_u32(const void* p) {
    uint32_t a;
    asm("{ .reg .u64 t; cvta.to.shared.u64 t, %1; cvt.u32.u64 %0, t; }" : "=r"(a) : "l"(p));
    return a;
}
#define MBAR_INIT(a, n) asm volatile("mbarrier.init.shared.b64 [%0], %1;" :: "r"(a), "r"(n) : "memory")
#define MBAR_WAIT(a, ph) do {                                                            \
    uint32_t _m = (a), _p = (ph), _d;                                                    \
    asm volatile("{ .reg .pred p; mbarrier.try_wait.parity.acquire.cta.shared::cta.b64 " \
                 "p, [%1], %2; selp.b32 %0, 1, 0, p; }" : "=r"(_d) : "r"(_m), "r"(_p) : "memory"); \
    if (!_d) {                                                                           \
        asm volatile("{ .reg .pred P1; WL_%=: mbarrier.try_wait.parity.acquire.cta.shared::cta.b64 " \
                     "P1, [%0], %1, 0x989680; @P1 bra.uni WD_%=; bra.uni WL_%=; WD_%=: }" \
                     :: "r"(_m), "r"(_p) : "memory");                                    \
    }                                                                                    \
} while (0)

#define LDSM_X4(r, a)                                                         \
    asm volatile("ldmatrix.sync.aligned.m8n8.x4.shared.b16 {%0,%1,%2,%3}, [%4];" \
        : "=r"((r)[0]), "=r"((r)[1]), "=r"((r)[2]), "=r"((r)[3]) : "r"(a))
#define LDSM_X4T(r, a)                                                        \
    asm volatile("ldmatrix.sync.aligned.m8n8.x4.trans.shared.b16 {%0,%1,%2,%3}, [%4];" \
        : "=r"((r)[0]), "=r"((r)[1]), "=r"((r)[2]), "=r"((r)[3]) : "r"(a))
#define LDSM_X2T(r, a)                                                        \
    asm volatile("ldmatrix.sync.aligned.m8n8.x2.trans.shared.b16 {%0,%1}, [%2];" \
        : "=r"((r)[0]), "=r"((r)[1]) : "r"(a))

#define MMA(d, a, b0_, b1_)                                                   \
    asm volatile("mma.sync.aligned.m16n8k16.row.col.f32.bf16.bf16.f32 "       \
        "{%0,%1,%2,%3},{%4,%5,%6,%7},{%8,%9},{%0,%1,%2,%3};"                  \
        : "+f"((d)[0]), "+f"((d)[1]), "+f"((d)[2]), "+f"((d)[3])              \
        : "r"((a)[0]), "r"((a)[1]), "r"((a)[2]), "r"((a)[3]), "r"(b0_), "r"(b1_))

// ---------------------------------------------------------------------------
// Kernel 1: adjacency bitpack (transposed)
// ---------------------------------------------------------------------------
__global__ void k_bitpack(const int* __restrict__ adj) {
    int gw = (blockIdx.x * 256 + threadIdx.x) >> 5;
    int lane = threadIdx.x & 31;
    int row = gw >> 7, wc = gw & 127;
    unsigned m = __ballot_sync(0xffffffffu, adj[row * NN + wc * 32 + lane] > 0);
    if (lane == 0) g_adjT[wc][row] = m;
}

// ---------------------------------------------------------------------------
// Kernel 2: xt = x @ W (per head)
// ---------------------------------------------------------------------------
__global__ __launch_bounds__(256) void k_xt(const float* __restrict__ x,
                                            const float* __restrict__ W) {
    __shared__ float sx[16][68];
    __shared__ float sw[16][64];
    const int h = blockIdx.y, n0 = blockIdx.x * 64, t = threadIdx.x;
    const int tx = t & 15, ty = t >> 4;
    const float* Wh = W + h * INF * OF;

    float acc[4][4] = {};
    for (int k0 = 0; k0 < INF; k0 += 16) {
        const int n = t >> 2, kq = (t & 3) * 4;
        float4 xv = *(const float4*)(x + (n0 + n) * INF + k0 + kq);
        const int kk = t & 15, f4 = t >> 4;
        float4 wv = *(const float4*)(Wh + (kk + k0) * OF + f4 * 4);
        __syncthreads();
        sx[kq + 0][n] = xv.x; sx[kq + 1][n] = xv.y;
        sx[kq + 2][n] = xv.z; sx[kq + 3][n] = xv.w;
        *(float4*)&sw[kk][f4 * 4] = wv;
        __syncthreads();
        #pragma unroll
        for (int k = 0; k < 16; k++) {
            float4 av = *(float4*)&sx[k][ty * 4];
            float4 bv = *(float4*)&sw[k][tx * 4];
            acc[0][0] += av.x * bv.x; acc[0][1] += av.x * bv.y; acc[0][2] += av.x * bv.z; acc[0][3] += av.x * bv.w;
            acc[1][0] += av.y * bv.x; acc[1][1] += av.y * bv.y; acc[1][2] += av.y * bv.z; acc[1][3] += av.y * bv.w;
            acc[2][0] += av.z * bv.x; acc[2][1] += av.z * bv.y; acc[2][2] += av.z * bv.z; acc[2][3] += av.z * bv.w;
            acc[3][0] += av.w * bv.x; acc[3][1] += av.w * bv.y; acc[3][2] += av.w * bv.z; acc[3][3] += av.w * bv.w;
        }
    }
    #pragma unroll
    for (int r = 0; r < 4; r++) {
        float4 o = make_float4(acc[r][0], acc[r][1], acc[r][2], acc[r][3]);
        *(float4*)&g_xt[h][n0 + ty * 4 + r][tx * 4] = o;
    }
}

// ---------------------------------------------------------------------------
// Kernel 3: per-(h,n) scalars
// ---------------------------------------------------------------------------
__global__ void k_rowdat(const float* __restrict__ a) {
    int gid = (blockIdx.x * 256 + threadIdx.x) >> 5;
    int lane = threadIdx.x & 31;
    int h = gid >> 12, n = gid & (NN - 1);
    const float* xr = g_xt[h][n];
    const float* ah = a + h * 2 * OF;
    float v0 = xr[lane], v1 = xr[lane + 32];
    float src = v0 * ah[lane] + v1 * ah[lane + 32];
    float dst = v0 * ah[64 + lane] + v1 * ah[96 + lane];
    #pragma unroll
    for (int s = 16; s; s >>= 1) {
        src += __shfl_xor_sync(0xffffffffu, src, s);
        dst += __shfl_xor_sync(0xffffffffu, dst, s);
    }
    if (lane == 0) {
        g_idat[h][n] = make_float4(src, expf(src), expf(0.2f * src), 0.f);
        g_jdat[h][n] = make_float4(dst, expf(dst), expf(0.2f * dst), 0.f);
    }
}

// ---------------------------------------------------------------------------
// Kernel 4: build bf16 V tiles, row-major [k][72], 144B rows (no swizzle).
// ---------------------------------------------------------------------------
__global__ __launch_bounds__(256) void k_vt() {
    __shared__ float sx[64][65];
    __shared__ float sE[2][64];
    const int c = blockIdx.x, h = blockIdx.y, j0 = c * 64, t = threadIdx.x;
    char* tb = g_Vt + (size_t)(h * 64 + c) * VCH;

    for (int idx = t; idx < 64 * 16; idx += 256) {
        int row = idx >> 4, f4 = idx & 15;
        float4 v = *(const float4*)&g_xt[h][j0 + row][f4 * 4];
        sx[row][f4 * 4 + 0] = v.x; sx[row][f4 * 4 + 1] = v.y;
        sx[row][f4 * 4 + 2] = v.z; sx[row][f4 * 4 + 3] = v.w;
    }
    if (t < 64) {
        float4 jd = g_jdat[h][j0 + t];
        sE[0][t] = jd.y; sE[1][t] = jd.z;
    }
    __syncthreads();

    for (int idx = t; idx < 64 * 36; idx += 256) {
        int k = idx / 36, u = idx % 36;
        int n0 = u * 2;
        #pragma unroll
        for (int m = 0; m < 2; m++) {
            float v0, v1;
            if (n0 < 64)       { v0 = sE[m][k] * sx[k][n0]; v1 = sE[m][k] * sx[k][n0 + 1]; }
            else if (n0 == 64) { v0 = sE[m][k];             v1 = 0.f; }
            else               { v0 = 0.f;                  v1 = 0.f; }
            __nv_bfloat16 h0 = __float2bfloat16(v0);
            __nv_bfloat16 h1 = __float2bfloat16(v1);
            float r0 = v0 - __bfloat162float(h0);
            float r1 = v1 - __bfloat162float(h1);
            __nv_bfloat16 l0 = __float2bfloat16(r0);
            __nv_bfloat16 l1 = __float2bfloat16(r1);
            uint32_t hv = (uint32_t)(*(unsigned short*)&h0) | ((uint32_t)(*(unsigned short*)&h1) << 16);
            uint32_t lv = (uint32_t)(*(unsigned short*)&l0) | ((uint32_t)(*(unsigned short*)&l1) << 16);
            *(uint32_t*)(tb + (2 * m) * SEGB + k * 144 + u * 4)     = hv;
            *(uint32_t*)(tb + (2 * m + 1) * SEGB + k * 144 + u * 4) = lv;
        }
    }
}

// ---------------------------------------------------------------------------
// Kernel 5 (main): mma.sync bf16 pipeline. 256 threads = 8 warps, M-split.
// Per chunk: stage A builds P1/P2 {0,1} bf16 tiles, stage B HMMA.
// V streams via double-buffered cp.async.bulk + mbarrier.
// ---------------------------------------------------------------------------
#define SM_V  0        // 2 x 36864
#define SM_P  73728    // P1: 128 x 144B
#define SM_P2 92160    // P2
#define SM_MB 110592   // 2 mbarriers
#define SM_TOT 110624

__global__ __launch_bounds__(256, 1) void k_main(float* __restrict__ out) {
    extern __shared__ char smem[];
    const uint32_t sb = smem_u32(smem);
    const int h = blockIdx.y, i0 = blockIdx.x * 128;
    const int t = threadIdx.x, wid = t >> 5, lane = t & 31;
    const uint32_t mb = sb + SM_MB;

    if (t == 0) { MBAR_INIT(mb, 1); MBAR_INIT(mb + 8, 1); }
    __syncthreads();
    if (t == 0) {
        asm volatile("mbarrier.arrive.expect_tx.shared.b64 _, [%0], %1;"
                     :: "r"(mb), "r"((uint32_t)VCH) : "memory");
        const char* src = g_Vt + (size_t)(h * 64) * VCH;
        uint64_t sg; asm("cvta.to.global.u64 %0, %1;" : "=l"(sg) : "l"(src));
        asm volatile("cp.async.bulk.shared::cluster.global.mbarrier::complete_tx::bytes "
                     "[%0], [%1], %2, [%3];"
                     :: "r"(sb + SM_V), "l"(sg), "r"((uint32_t)VCH), "r"(mb) : "memory");
    }

    // stage-A identity: half = j-half (0/1), rA = i-row 0..127
    const int half = t >> 7, rA = t & 127;
    const float th = -g_idat[h][i0 + rA].x;   // P1: dst >= -src

    // accumulators: D1, D2, 9 n-tiles each
    float d1[9][4], d2[9][4];
    #pragma unroll
    for (int nt = 0; nt < 9; nt++) {
        d1[nt][0] = d1[nt][1] = d1[nt][2] = d1[nt][3] = 0.f;
        d2[nt][0] = d2[nt][1] = d2[nt][2] = d2[nt][3] = 0.f;
    }

    // ldmatrix base addresses
    const uint32_t a1base = sb + SM_P  + (uint32_t)(wid * 16 + (lane & 15)) * 144 + (lane >> 4) * 16;
    const uint32_t a2base = a1base + (SM_P2 - SM_P);
    const uint32_t bOff   = (uint32_t)(lane & 15) * 144 + (lane >> 4) * 16;
    const uint32_t b8Off  = (uint32_t)(lane & 15) * 144 + 128;

    int ph0 = 0, ph1 = 0;
    for (int m = 0; m < 64; m++) {
        const int b = m & 1;
        const uint32_t vb = sb + SM_V + b * VCH;
        __syncthreads();   // prev stage B done reading Pbuf and buf[1-b]
        if (t == 0 && m + 1 < 64) {
            uint32_t nmb = mb + (1 - b) * 8;
            asm volatile("mbarrier.arrive.expect_tx.shared.b64 _, [%0], %1;"
                         :: "r"(nmb), "r"((uint32_t)VCH) : "memory");
            const char* src = g_Vt + (size_t)(h * 64 + m + 1) * VCH;
            uint64_t sg; asm("cvta.to.global.u64 %0, %1;" : "=l"(sg) : "l"(src));
            asm volatile("cp.async.bulk.shared::cluster.global.mbarrier::complete_tx::bytes "
                         "[%0], [%1], %2, [%3];"
                         :: "r"(sb + SM_V + (1 - b) * VCH), "l"(sg), "r"((uint32_t)VCH), "r"(nmb)
                         : "memory");
        }
        // ---------------- stage A: P1/P2 tiles ----------------
        {
            float dl = g_jdat[h][m * 64 + half * 32 + lane].x;
            unsigned word = g_adjT[2 * m + half][i0 + rA];
            uint32_t v1[16], v2[16];
            #pragma unroll
            for (int p = 0; p < 16; p++) {
                float e0 = __shfl_sync(0xffffffffu, dl, 2 * p);
                float e1 = __shfl_sync(0xffffffffu, dl, 2 * p + 1);
                unsigned m0 = ((word >> (2 * p)) & 1u) ? 0x3F80u : 0u;
                unsigned m1 = ((word >> (2 * p + 1)) & 1u) ? 0x3F80u : 0u;
                unsigned x0 = (e0 >= th) ? m0 : 0u;
                unsigned x1 = (e1 >= th) ? m1 : 0u;
                v1[p] = x0 | (x1 << 16);
                v2[p] = (m0 ^ x0) | ((m1 ^ x1) << 16);
            }
            char* prow = smem + SM_P + rA * 144 + half * 64;
            #pragma unroll
            for (int q = 0; q < 4; q++) {
                *(uint4*)(prow + q * 16) =
                    make_uint4(v1[q * 4], v1[q * 4 + 1], v1[q * 4 + 2], v1[q * 4 + 3]);
                *(uint4*)(prow + (SM_P2 - SM_P) + q * 16) =
                    make_uint4(v2[q * 4], v2[q * 4 + 1], v2[q * 4 + 2], v2[q * 4 + 3]);
            }
        }
        __syncthreads();   // P tiles ready
        if (b == 0) { MBAR_WAIT(mb, ph0); ph0 ^= 1; }
        else        { MBAR_WAIT(mb + 8, ph1); ph1 ^= 1; }
        // ---------------- stage B: HMMA ----------------
        #pragma unroll
        for (int ks = 0; ks < 4; ks++) {
            uint32_t a1f[4], a2f[4];
            LDSM_X4(a1f, a1base + ks * 32);
            LDSM_X4(a2f, a2base + ks * 32);
            const uint32_t kb = vb + (uint32_t)ks * 16 * 144;
            #pragma unroll
            for (int g = 0; g < 4; g++) {
                uint32_t bf[4];
                const uint32_t gb = kb + bOff + g * 32;
                LDSM_X4T(bf, gb + 0 * SEGB);
                MMA(d1[2 * g], a1f, bf[0], bf[1]); MMA(d1[2 * g + 1], a1f, bf[2], bf[3]);
                LDSM_X4T(bf, gb + 1 * SEGB);
                MMA(d1[2 * g], a1f, bf[0], bf[1]); MMA(d1[2 * g + 1], a1f, bf[2], bf[3]);
                LDSM_X4T(bf, gb + 2 * SEGB);
                MMA(d2[2 * g], a2f, bf[0], bf[1]); MMA(d2[2 * g + 1], a2f, bf[2], bf[3]);
                LDSM_X4T(bf, gb + 3 * SEGB);
                MMA(d2[2 * g], a2f, bf[0], bf[1]); MMA(d2[2 * g + 1], a2f, bf[2], bf[3]);
            }
            {
                uint32_t c2[2];
                const uint32_t t8 = kb + b8Off;
                LDSM_X2T(c2, t8 + 0 * SEGB); MMA(d1[8], a1f, c2[0], c2[1]);
                LDSM_X2T(c2, t8 + 1 * SEGB); MMA(d1[8], a1f, c2[0], c2[1]);
                LDSM_X2T(c2, t8 + 2 * SEGB); MMA(d2[8], a2f, c2[0], c2[1]);
                LDSM_X2T(c2, t8 + 3 * SEGB); MMA(d2[8], a2f, c2[0], c2[1]);
            }
        }
    }

    // ---------------- epilogue ----------------
    const int rloc = lane >> 2;
    const int ia_ = i0 + wid * 16 + rloc, ib_ = ia_ + 8;
    float z1a = __shfl_sync(0xffffffffu, d1[8][0], rloc * 4);
    float z2a = __shfl_sync(0xffffffffu, d2[8][0], rloc * 4);
    float z1b = __shfl_sync(0xffffffffu, d1[8][2], rloc * 4);
    float z2b = __shfl_sync(0xffffffffu, d2[8][2], rloc * 4);
    float4 va = g_idat[h][ia_], vb4 = g_idat[h][ib_];
    float zia = 1.0f / (va.y * z1a + va.z * z2a);
    float zib = 1.0f / (vb4.y * z1b + vb4.z * z2b);
    float* oa = out + (size_t)ia_ * (NH * OF) + h * OF + (lane & 3) * 2;
    float* ob = out + (size_t)ib_ * (NH * OF) + h * OF + (lane & 3) * 2;
    #pragma unroll
    for (int nt = 0; nt < 8; nt++) {
        float2 pa, pb;
        pa.x = (va.y * d1[nt][0] + va.z * d2[nt][0]) * zia;
        pa.y = (va.y * d1[nt][1] + va.z * d2[nt][1]) * zia;
        pb.x = (vb4.y * d1[nt][2] + vb4.z * d2[nt][2]) * zib;
        pb.y = (vb4.y * d1[nt][3] + vb4.z * d2[nt][3]) * zib;
        *(float2*)(oa + nt * 8) = pa;
        *(float2*)(ob + nt * 8) = pb;
    }
}

// ---------------------------------------------------------------------------
extern "C" void kernel_launch(void* const* d_in, const int* in_sizes, int n_in,
                              void* d_out, int out_size) {
    const float* x   = (const float*)d_in[0];  // [4096, 256]
    const float* W   = (const float*)d_in[1];  // [4, 256, 64]
    const float* a   = (const float*)d_in[2];  // [4, 128]
    const int*   adj = (const int*)d_in[3];    // [4096, 4096]
    float* out = (float*)d_out;                // [4096, 256]
    (void)in_sizes; (void)n_in; (void)out_size;

    cudaFuncSetAttribute(k_main, cudaFuncAttributeMaxDynamicSharedMemorySize, SM_TOT);

    k_bitpack<<<(NN * (NN / 32)) / 8, 256>>>(adj);
    k_xt<<<dim3(NN / 64, NH), 256>>>(x, W);
    k_rowdat<<<(NH * NN) / 8, 256>>>(a);
    k_vt<<<dim3(64, NH), 256>>>();
    k_main<<<dim3(NN / 128, NH), 256, SM_TOT>>>(out);
}

// round 5
// speedup vs baseline: 1.6729x; 1.1102x over previous
#include <cuda_runtime.h>
#include <cuda_bf16.h>
#include <cstdint>

#define NN 4096
#define INF 256
#define OF 64
#define NH 4

// ---------------------------------------------------------------------------
// Scratch globals
// ---------------------------------------------------------------------------
__device__ float4   g_idat[NH][NN];        // {src, exp(src), exp(0.2*src), 0}
__device__ float4   g_jdat[NH][NN];        // {dst, exp(dst), exp(0.2*dst), 0}
__device__ unsigned g_adjT[NN / 32][NN];   // adjacency bits [wordcol][row]
// V tiles: per (h,chunk): 4 segs (V1hi,V1lo,V2hi,V2lo), each [64 k][64 n] bf16,
// row stride 144B (ldmatrix conflict-free; cols 64..71 pad, never read).
#define SEGB 9216
#define VCH  (4 * SEGB)
__device__ __align__(16) char g_Vt[NH * 64 * VCH];

// ---------------------------------------------------------------------------
// PTX helpers (family-generic: no tcgen05 on compute_103 virtual target)
// ---------------------------------------------------------------------------
__device__ __forceinline__ uint32_t smem_u32(const void* p) {
    uint32_t a;
    asm("{ .reg .u64 t; cvta.to.shared.u64 t, %1; cvt.u32.u64 %0, t; }" : "=r"(a) : "l"(p));
    return a;
}
#define MBAR_INIT(a, n) asm volatile("mbarrier.init.shared.b64 [%0], %1;" :: "r"(a), "r"(n) : "memory")
#define MBAR_WAIT(a, ph) do {                                                            \
    uint32_t _m = (a), _p = (ph), _d;                                                    \
    asm volatile("{ .reg .pred p; mbarrier.try_wait.parity.acquire.cta.shared::cta.b64 " \
                 "p, [%1], %2; selp.b32 %0, 1, 0, p; }" : "=r"(_d) : "r"(_m), "r"(_p) : "memory"); \
    if (!_d) {                                                                           \
        asm volatile("{ .reg .pred P1; WL_%=: mbarrier.try_wait.parity.acquire.cta.shared::cta.b64 " \
                     "P1, [%0], %1, 0x989680; @P1 bra.uni WD_%=; bra.uni WL_%=; WD_%=: }" \
                     :: "r"(_m), "r"(_p) : "memory");                                    \
    }                                                                                    \
} while (0)

#define LDSM_X4(r, a)                                                         \
    asm volatile("ldmatrix.sync.aligned.m8n8.x4.shared.b16 {%0,%1,%2,%3}, [%4];" \
        : "=r"((r)[0]), "=r"((r)[1]), "=r"((r)[2]), "=r"((r)[3]) : "r"(a))
#define LDSM_X4T(r, a)                                                        \
    asm volatile("ldmatrix.sync.aligned.m8n8.x4.trans.shared.b16 {%0,%1,%2,%3}, [%4];" \
        : "=r"((r)[0]), "=r"((r)[1]), "=r"((r)[2]), "=r"((r)[3]) : "r"(a))

#define MMA(d, a, b0_, b1_)                                                   \
    asm volatile("mma.sync.aligned.m16n8k16.row.col.f32.bf16.bf16.f32 "       \
        "{%0,%1,%2,%3},{%4,%5,%6,%7},{%8,%9},{%0,%1,%2,%3};"                  \
        : "+f"((d)[0]), "+f"((d)[1]), "+f"((d)[2]), "+f"((d)[3])              \
        : "r"((a)[0]), "r"((a)[1]), "r"((a)[2]), "r"((a)[3]), "r"(b0_), "r"(b1_))

// ---------------------------------------------------------------------------
// Kernel 1: adjacency bitpack (transposed), int4-vectorized
// ---------------------------------------------------------------------------
__global__ __launch_bounds__(256) void k_bitpack(const int* __restrict__ adj) {
    int tg = blockIdx.x * 256 + threadIdx.x;
    int lane = threadIdx.x & 31;
    int idx4 = tg * 4;
    int row = idx4 >> 12, col4 = idx4 & 4095;
    int4 v = *(const int4*)(adj + (size_t)row * NN + col4);
    unsigned nib = (unsigned)(v.x > 0) | ((unsigned)(v.y > 0) << 1) |
                   ((unsigned)(v.z > 0) << 2) | ((unsigned)(v.w > 0) << 3);
    unsigned val = nib << (((unsigned)(col4 >> 2) & 7u) * 4u);
    val |= __shfl_xor_sync(0xffffffffu, val, 1);
    val |= __shfl_xor_sync(0xffffffffu, val, 2);
    val |= __shfl_xor_sync(0xffffffffu, val, 4);
    if ((lane & 7) == 0) g_adjT[col4 >> 5][row] = val;
}

// ---------------------------------------------------------------------------
// Kernel 2 (fused): xt GEMM + per-row scalars + V-tile build.
// Block = (chunk c = 64 nodes, head h), 256 threads.
// ---------------------------------------------------------------------------
__global__ __launch_bounds__(256) void k_xtv(const float* __restrict__ x,
                                             const float* __restrict__ W,
                                             const float* __restrict__ a) {
    __shared__ float sx[16][68];
    __shared__ float sw[16][64];
    __shared__ float sxt[64][68];
    __shared__ float sE[2][64];
    const int h = blockIdx.y, n0 = blockIdx.x * 64, t = threadIdx.x;
    const int tx = t & 15, ty = t >> 4;
    const float* Wh = W + h * INF * OF;

    // phase 1: xt tile GEMM (rows = nodes n0..n0+63, cols = 64 features)
    float acc[4][4] = {};
    for (int k0 = 0; k0 < INF; k0 += 16) {
        const int n = t >> 2, kq = (t & 3) * 4;
        float4 xv = *(const float4*)(x + (n0 + n) * INF + k0 + kq);
        const int kk = t & 15, f4 = t >> 4;
        float4 wv = *(const float4*)(Wh + (kk + k0) * OF + f4 * 4);
        __syncthreads();
        sx[kq + 0][n] = xv.x; sx[kq + 1][n] = xv.y;
        sx[kq + 2][n] = xv.z; sx[kq + 3][n] = xv.w;
        *(float4*)&sw[kk][f4 * 4] = wv;
        __syncthreads();
        #pragma unroll
        for (int k = 0; k < 16; k++) {
            float4 av = *(float4*)&sx[k][ty * 4];
            float4 bv = *(float4*)&sw[k][tx * 4];
            acc[0][0] += av.x * bv.x; acc[0][1] += av.x * bv.y; acc[0][2] += av.x * bv.z; acc[0][3] += av.x * bv.w;
            acc[1][0] += av.y * bv.x; acc[1][1] += av.y * bv.y; acc[1][2] += av.y * bv.z; acc[1][3] += av.y * bv.w;
            acc[2][0] += av.z * bv.x; acc[2][1] += av.z * bv.y; acc[2][2] += av.z * bv.z; acc[2][3] += av.z * bv.w;
            acc[3][0] += av.w * bv.x; acc[3][1] += av.w * bv.y; acc[3][2] += av.w * bv.z; acc[3][3] += av.w * bv.w;
        }
    }
    __syncthreads();
    #pragma unroll
    for (int r = 0; r < 4; r++)
        *(float4*)&sxt[ty * 4 + r][tx * 4] = make_float4(acc[r][0], acc[r][1], acc[r][2], acc[r][3]);
    __syncthreads();

    // phase 2: per-row src/dst dots (4 threads per row)
    {
        const int row = t >> 2, q = t & 3;
        const float* ah = a + h * 2 * OF;
        float s = 0.f, d = 0.f;
        #pragma unroll
        for (int ff = 0; ff < 16; ff++) {
            int f = q * 16 + ff;
            float v = sxt[row][f];
            s += v * ah[f];
            d += v * ah[OF + f];
        }
        s += __shfl_xor_sync(0xffffffffu, s, 1); s += __shfl_xor_sync(0xffffffffu, s, 2);
        d += __shfl_xor_sync(0xffffffffu, d, 1); d += __shfl_xor_sync(0xffffffffu, d, 2);
        if (q == 0) {
            float e1 = expf(d), e2 = expf(0.2f * d);
            g_idat[h][n0 + row] = make_float4(s, expf(s), expf(0.2f * s), 0.f);
            g_jdat[h][n0 + row] = make_float4(d, e1, e2, 0.f);
            sE[0][row] = e1; sE[1][row] = e2;
        }
    }
    __syncthreads();

    // phase 3: V tiles (hi/lo bf16, row stride 144B)
    char* tb = g_Vt + (size_t)(h * 64 + blockIdx.x) * VCH;
    for (int idx = t; idx < 64 * 32; idx += 256) {
        int k = idx >> 5, u = idx & 31;
        int c0 = u * 2;
        #pragma unroll
        for (int m = 0; m < 2; m++) {
            float e = sE[m][k];
            float v0 = e * sxt[k][c0], v1 = e * sxt[k][c0 + 1];
            __nv_bfloat16 h0 = __float2bfloat16(v0);
            __nv_bfloat16 h1 = __float2bfloat16(v1);
            float r0 = v0 - __bfloat162float(h0);
            float r1 = v1 - __bfloat162float(h1);
            __nv_bfloat16 l0 = __float2bfloat16(r0);
            __nv_bfloat16 l1 = __float2bfloat16(r1);
            uint32_t hv = (uint32_t)(*(unsigned short*)&h0) | ((uint32_t)(*(unsigned short*)&h1) << 16);
            uint32_t lv = (uint32_t)(*(unsigned short*)&l0) | ((uint32_t)(*(unsigned short*)&l1) << 16);
            *(uint32_t*)(tb + (2 * m) * SEGB + k * 144 + u * 4)     = hv;
            *(uint32_t*)(tb + (2 * m + 1) * SEGB + k * 144 + u * 4) = lv;
        }
    }
}

// ---------------------------------------------------------------------------
// Kernel 3 (main): HMMA pipeline, 2D warp tile (Mw=2 x Nw=4), Z in stage A.
// ---------------------------------------------------------------------------
#define SM_V   0                      // 2 x 36864
#define SM_P1  73728                  // 128 x 144
#define SM_P2  92160
#define SM_Z   110592                 // 4 x 128 floats
#define SM_MB  112640
#define SM_TOT 112672

__global__ __launch_bounds__(256, 1) void k_main(float* __restrict__ out) {
    extern __shared__ char smem[];
    const uint32_t sb = smem_u32(smem);
    const int h = blockIdx.y, i0 = blockIdx.x * 128;
    const int t = threadIdx.x, wid = t >> 5, lane = t & 31;
    const uint32_t mb = sb + SM_MB;

    if (t == 0) { MBAR_INIT(mb, 1); MBAR_INIT(mb + 8, 1); }
    __syncthreads();
    if (t == 0) {
        asm volatile("mbarrier.arrive.expect_tx.shared.b64 _, [%0], %1;"
                     :: "r"(mb), "r"((uint32_t)VCH) : "memory");
        const char* src = g_Vt + (size_t)(h * 64) * VCH;
        uint64_t sg; asm("cvta.to.global.u64 %0, %1;" : "=l"(sg) : "l"(src));
        asm volatile("cp.async.bulk.shared::cluster.global.mbarrier::complete_tx::bytes "
                     "[%0], [%1], %2, [%3];"
                     :: "r"(sb + SM_V), "l"(sg), "r"((uint32_t)VCH), "r"(mb) : "memory");
    }

    // stage-A identity: half = j-half (0/1), rA = i-row 0..127
    const int half = t >> 7, rA = t & 127;
    const float th = -g_idat[h][i0 + rA].x;   // P1: dst >= -src
    float z1acc = 0.f, z2acc = 0.f;

    // stage-B identity: mgrp (rows mgrp*64..+63), ngrp (cols ngrp*16..+15)
    const int mgrp = wid >> 2, ngrp = wid & 3;
    float d1[8][4], d2[8][4];
    #pragma unroll
    for (int q = 0; q < 8; q++) {
        d1[q][0] = d1[q][1] = d1[q][2] = d1[q][3] = 0.f;
        d2[q][0] = d2[q][1] = d2[q][2] = d2[q][3] = 0.f;
    }

    const uint32_t aOff = (uint32_t)((mgrp * 64 + (lane & 15)) * 144 + (lane >> 4) * 16);
    const uint32_t a1base = sb + SM_P1 + aOff;
    const uint32_t a2base = sb + SM_P2 + aOff;
    const uint32_t bOff = (uint32_t)((lane & 15) * 144 + (lane >> 4) * 16 + ngrp * 32);

    int ph0 = 0, ph1 = 0;
    for (int m = 0; m < 64; m++) {
        const int b = m & 1;
        const uint32_t vb = sb + SM_V + b * VCH;
        __syncthreads();   // prev stage B done reading P tiles and buf[1-b]
        if (t == 0 && m + 1 < 64) {
            uint32_t nmb = mb + (1 - b) * 8;
            asm volatile("mbarrier.arrive.expect_tx.shared.b64 _, [%0], %1;"
                         :: "r"(nmb), "r"((uint32_t)VCH) : "memory");
            const char* src = g_Vt + (size_t)(h * 64 + m + 1) * VCH;
            uint64_t sg; asm("cvta.to.global.u64 %0, %1;" : "=l"(sg) : "l"(src));
            asm volatile("cp.async.bulk.shared::cluster.global.mbarrier::complete_tx::bytes "
                         "[%0], [%1], %2, [%3];"
                         :: "r"(sb + SM_V + (1 - b) * VCH), "l"(sg), "r"((uint32_t)VCH), "r"(nmb)
                         : "memory");
        }
        // ---------------- stage A: P1/P2 tiles + Z partials ----------------
        {
            float4 jd = g_jdat[h][m * 64 + half * 32 + lane];
            unsigned word = g_adjT[2 * m + half][i0 + rA];
            uint32_t v1[16], v2[16];
            #pragma unroll
            for (int p = 0; p < 16; p++) {
                float dd0 = __shfl_sync(0xffffffffu, jd.x, 2 * p);
                float dd1 = __shfl_sync(0xffffffffu, jd.x, 2 * p + 1);
                float e10 = __shfl_sync(0xffffffffu, jd.y, 2 * p);
                float e11 = __shfl_sync(0xffffffffu, jd.y, 2 * p + 1);
                float e20 = __shfl_sync(0xffffffffu, jd.z, 2 * p);
                float e21 = __shfl_sync(0xffffffffu, jd.z, 2 * p + 1);
                unsigned m0 = ((word >> (2 * p)) & 1u) ? 0x3F80u : 0u;
                unsigned m1 = ((word >> (2 * p + 1)) & 1u) ? 0x3F80u : 0u;
                unsigned x0 = (dd0 >= th) ? m0 : 0u;
                unsigned x1 = (dd1 >= th) ? m1 : 0u;
                unsigned y0 = m0 ^ x0, y1 = m1 ^ x1;
                v1[p] = x0 | (x1 << 16);
                v2[p] = y0 | (y1 << 16);
                z1acc += (x0 ? e10 : 0.f) + (x1 ? e11 : 0.f);
                z2acc += (y0 ? e20 : 0.f) + (y1 ? e21 : 0.f);
            }
            char* prow = smem + SM_P1 + rA * 144 + half * 64;
            #pragma unroll
            for (int q = 0; q < 4; q++) {
                *(uint4*)(prow + q * 16) =
                    make_uint4(v1[q * 4], v1[q * 4 + 1], v1[q * 4 + 2], v1[q * 4 + 3]);
                *(uint4*)(prow + (SM_P2 - SM_P1) + q * 16) =
                    make_uint4(v2[q * 4], v2[q * 4 + 1], v2[q * 4 + 2], v2[q * 4 + 3]);
            }
        }
        __syncthreads();   // P tiles ready
        if (b == 0) { MBAR_WAIT(mb, ph0); ph0 ^= 1; }
        else        { MBAR_WAIT(mb + 8, ph1); ph1 ^= 1; }
        // ---------------- stage B: HMMA ----------------
        #pragma unroll
        for (int ks = 0; ks < 4; ks++) {
            uint32_t a1f[4][4], a2f[4][4];
            #pragma unroll
            for (int mt = 0; mt < 4; mt++) {
                LDSM_X4(a1f[mt], a1base + mt * 2304 + ks * 32);
                LDSM_X4(a2f[mt], a2base + mt * 2304 + ks * 32);
            }
            const uint32_t kb = vb + (uint32_t)ks * 2304 + bOff;
            uint32_t bf[4];
            LDSM_X4T(bf, kb + 0 * SEGB);
            #pragma unroll
            for (int mt = 0; mt < 4; mt++) {
                MMA(d1[mt * 2], a1f[mt], bf[0], bf[1]);
                MMA(d1[mt * 2 + 1], a1f[mt], bf[2], bf[3]);
            }
            LDSM_X4T(bf, kb + 1 * SEGB);
            #pragma unroll
            for (int mt = 0; mt < 4; mt++) {
                MMA(d1[mt * 2], a1f[mt], bf[0], bf[1]);
                MMA(d1[mt * 2 + 1], a1f[mt], bf[2], bf[3]);
            }
            LDSM_X4T(bf, kb + 2 * SEGB);
            #pragma unroll
            for (int mt = 0; mt < 4; mt++) {
                MMA(d2[mt * 2], a2f[mt], bf[0], bf[1]);
                MMA(d2[mt * 2 + 1], a2f[mt], bf[2], bf[3]);
            }
            LDSM_X4T(bf, kb + 3 * SEGB);
            #pragma unroll
            for (int mt = 0; mt < 4; mt++) {
                MMA(d2[mt * 2], a2f[mt], bf[0], bf[1]);
                MMA(d2[mt * 2 + 1], a2f[mt], bf[2], bf[3]);
            }
        }
    }

    // ---------------- Z reduction ----------------
    float* zs = (float*)(smem + SM_Z);   // [4][128]: z1h0, z1h1, z2h0, z2h1
    __syncthreads();
    zs[half * 128 + rA] = z1acc;
    zs[256 + half * 128 + rA] = z2acc;
    __syncthreads();

    // ---------------- epilogue ----------------
    #pragma unroll
    for (int mt = 0; mt < 4; mt++) {
        int rlo = mgrp * 64 + mt * 16 + (lane >> 2);
        int rhi = rlo + 8;
        float4 ia = g_idat[h][i0 + rlo];
        float4 ib = g_idat[h][i0 + rhi];
        float zlo = 1.0f / (ia.y * (zs[rlo] + zs[128 + rlo]) + ia.z * (zs[256 + rlo] + zs[384 + rlo]));
        float zhi = 1.0f / (ib.y * (zs[rhi] + zs[128 + rhi]) + ib.z * (zs[256 + rhi] + zs[384 + rhi]));
        #pragma unroll
        for (int n8 = 0; n8 < 2; n8++) {
            int col = h * OF + ngrp * 16 + n8 * 8 + (lane & 3) * 2;
            float* q1 = d1[mt * 2 + n8];
            float* q2 = d2[mt * 2 + n8];
            float2 plo, phi;
            plo.x = (ia.y * q1[0] + ia.z * q2[0]) * zlo;
            plo.y = (ia.y * q1[1] + ia.z * q2[1]) * zlo;
            phi.x = (ib.y * q1[2] + ib.z * q2[2]) * zhi;
            phi.y = (ib.y * q1[3] + ib.z * q2[3]) * zhi;
            *(float2*)(out + (size_t)(i0 + rlo) * (NH * OF) + col) = plo;
            *(float2*)(out + (size_t)(i0 + rhi) * (NH * OF) + col) = phi;
        }
    }
}

// ---------------------------------------------------------------------------
extern "C" void kernel_launch(void* const* d_in, const int* in_sizes, int n_in,
                              void* d_out, int out_size) {
    const float* x   = (const float*)d_in[0];  // [4096, 256]
    const float* W   = (const float*)d_in[1];  // [4, 256, 64]
    const float* a   = (const float*)d_in[2];  // [4, 128]
    const int*   adj = (const int*)d_in[3];    // [4096, 4096]
    float* out = (float*)d_out;                // [4096, 256]
    (void)in_sizes; (void)n_in; (void)out_size;

    cudaFuncSetAttribute(k_main, cudaFuncAttributeMaxDynamicSharedMemorySize, SM_TOT);

    k_bitpack<<<(NN * NN / 4) / 256, 256>>>(adj);
    k_xtv<<<dim3(NN / 64, NH), 256>>>(x, W, a);
    k_main<<<dim3(NN / 128, NH), 256, SM_TOT>>>(out);
}

// round 6
// speedup vs baseline: 1.7899x; 1.0699x over previous
#include <cuda_runtime.h>
#include <cuda_bf16.h>
#include <cstdint>

#define NN 4096
#define INF 256
#define OF 64
#define NH 4

// ---------------------------------------------------------------------------
// Scratch globals
// ---------------------------------------------------------------------------
__device__ float4   g_idat[NH][NN];        // {src, exp(src), exp(0.2*src), 0}
__device__ float4   g_jdat[NH][NN];        // {dst, exp(dst), exp(0.2*dst), 0}
__device__ unsigned g_adjT[NN / 32][NN];   // adjacency bits [wordcol][row]
// V tiles: per (h,chunk): 4 segs (V1hi,V1lo,V2hi,V2lo), each [64 k][72 n] bf16,
// row stride 144B. cols 0-63 = E*xt (hi or lo); col 64 = E (hi in hi-seg, lo in
// lo-seg) so Z accumulates in D col 64; cols 65-71 stay zero (never written).
#define SEGB 9216
#define VCH  (4 * SEGB)
__device__ __align__(16) char g_Vt[NH * 64 * VCH];

// ---------------------------------------------------------------------------
// PTX helpers (family-generic: no tcgen05 on compute_103 virtual target)
// ---------------------------------------------------------------------------
__device__ __forceinline__ uint32_t smem_u32(const void* p) {
    uint32_t a;
    asm("{ .reg .u64 t; cvta.to.shared.u64 t, %1; cvt.u32.u64 %0, t; }" : "=r"(a) : "l"(p));
    return a;
}
#define MBAR_INIT(a, n) asm volatile("mbarrier.init.shared.b64 [%0], %1;" :: "r"(a), "r"(n) : "memory")
#define MBAR_WAIT(a, ph) do {                                                            \
    uint32_t _m = (a), _p = (ph), _d;                                                    \
    asm volatile("{ .reg .pred p; mbarrier.try_wait.parity.acquire.cta.shared::cta.b64 " \
                 "p, [%1], %2; selp.b32 %0, 1, 0, p; }" : "=r"(_d) : "r"(_m), "r"(_p) : "memory"); \
    if (!_d) {                                                                           \
        asm volatile("{ .reg .pred P1; WL_%=: mbarrier.try_wait.parity.acquire.cta.shared::cta.b64 " \
                     "P1, [%0], %1, 0x989680; @P1 bra.uni WD_%=; bra.uni WL_%=; WD_%=: }" \
                     :: "r"(_m), "r"(_p) : "memory");                                    \
    }                                                                                    \
} while (0)
#define MBAR_ARRIVE(a) asm volatile("mbarrier.arrive.shared.b64 _, [%0];" :: "r"(a) : "memory")
#define BAR_SYNC(id, n) asm volatile("bar.sync %0, %1;" :: "r"(id), "r"(n) : "memory")

#define LDSM_X4(r, a)                                                         \
    asm volatile("ldmatrix.sync.aligned.m8n8.x4.shared.b16 {%0,%1,%2,%3}, [%4];" \
        : "=r"((r)[0]), "=r"((r)[1]), "=r"((r)[2]), "=r"((r)[3]) : "r"(a))
#define LDSM_X4T(r, a)                                                        \
    asm volatile("ldmatrix.sync.aligned.m8n8.x4.trans.shared.b16 {%0,%1,%2,%3}, [%4];" \
        : "=r"((r)[0]), "=r"((r)[1]), "=r"((r)[2]), "=r"((r)[3]) : "r"(a))
#define LDSM_X2T(r, a)                                                        \
    asm volatile("ldmatrix.sync.aligned.m8n8.x2.trans.shared.b16 {%0,%1}, [%2];" \
        : "=r"((r)[0]), "=r"((r)[1]) : "r"(a))

#define MMA(d, a, b0_, b1_)                                                   \
    asm volatile("mma.sync.aligned.m16n8k16.row.col.f32.bf16.bf16.f32 "       \
        "{%0,%1,%2,%3},{%4,%5,%6,%7},{%8,%9},{%0,%1,%2,%3};"                  \
        : "+f"((d)[0]), "+f"((d)[1]), "+f"((d)[2]), "+f"((d)[3])              \
        : "r"((a)[0]), "r"((a)[1]), "r"((a)[2]), "r"((a)[3]), "r"(b0_), "r"(b1_))

// ---------------------------------------------------------------------------
// Kernel 1: adjacency bitpack (transposed), 16 elements/thread (MLP=4)
// ---------------------------------------------------------------------------
__global__ __launch_bounds__(256) void k_bitpack(const int* __restrict__ adj) {
    size_t tid = (size_t)blockIdx.x * 256 + threadIdx.x;
    int lane = threadIdx.x & 31;
    size_t base = tid * 16;
    int row = (int)(base >> 12), col = (int)(base & 4095);
    unsigned bits = 0;
    #pragma unroll
    for (int e = 0; e < 4; e++) {
        int4 v = *(const int4*)(adj + (size_t)row * NN + col + e * 4);
        bits |= ((unsigned)(v.x > 0) << (e * 4)) | ((unsigned)(v.y > 0) << (e * 4 + 1)) |
                ((unsigned)(v.z > 0) << (e * 4 + 2)) | ((unsigned)(v.w > 0) << (e * 4 + 3));
    }
    unsigned val = bits << (((unsigned)(col >> 4) & 1u) * 16u);
    val |= __shfl_xor_sync(0xffffffffu, val, 1);
    if ((lane & 1) == 0) g_adjT[col >> 5][row] = val;
}

// ---------------------------------------------------------------------------
// Kernel 2 (fused): xt GEMM + per-row scalars + V-tile build.
// ---------------------------------------------------------------------------
__global__ __launch_bounds__(256) void k_xtv(const float* __restrict__ x,
                                             const float* __restrict__ W,
                                             const float* __restrict__ a) {
    __shared__ float sx[16][68];
    __shared__ float sw[16][64];
    __shared__ float sxt[64][68];
    __shared__ float sE[2][64];
    const int h = blockIdx.y, n0 = blockIdx.x * 64, t = threadIdx.x;
    const int tx = t & 15, ty = t >> 4;
    const float* Wh = W + h * INF * OF;

    float acc[4][4] = {};
    for (int k0 = 0; k0 < INF; k0 += 16) {
        const int n = t >> 2, kq = (t & 3) * 4;
        float4 xv = *(const float4*)(x + (n0 + n) * INF + k0 + kq);
        const int kk = t & 15, f4 = t >> 4;
        float4 wv = *(const float4*)(Wh + (kk + k0) * OF + f4 * 4);
        __syncthreads();
        sx[kq + 0][n] = xv.x; sx[kq + 1][n] = xv.y;
        sx[kq + 2][n] = xv.z; sx[kq + 3][n] = xv.w;
        *(float4*)&sw[kk][f4 * 4] = wv;
        __syncthreads();
        #pragma unroll
        for (int k = 0; k < 16; k++) {
            float4 av = *(float4*)&sx[k][ty * 4];
            float4 bv = *(float4*)&sw[k][tx * 4];
            acc[0][0] += av.x * bv.x; acc[0][1] += av.x * bv.y; acc[0][2] += av.x * bv.z; acc[0][3] += av.x * bv.w;
            acc[1][0] += av.y * bv.x; acc[1][1] += av.y * bv.y; acc[1][2] += av.y * bv.z; acc[1][3] += av.y * bv.w;
            acc[2][0] += av.z * bv.x; acc[2][1] += av.z * bv.y; acc[2][2] += av.z * bv.z; acc[2][3] += av.z * bv.w;
            acc[3][0] += av.w * bv.x; acc[3][1] += av.w * bv.y; acc[3][2] += av.w * bv.z; acc[3][3] += av.w * bv.w;
        }
    }
    __syncthreads();
    #pragma unroll
    for (int r = 0; r < 4; r++)
        *(float4*)&sxt[ty * 4 + r][tx * 4] = make_float4(acc[r][0], acc[r][1], acc[r][2], acc[r][3]);
    __syncthreads();

    {
        const int row = t >> 2, qq = t & 3;
        const float* ah = a + h * 2 * OF;
        float s = 0.f, d = 0.f;
        #pragma unroll
        for (int ff = 0; ff < 16; ff++) {
            int f = qq * 16 + ff;
            float v = sxt[row][f];
            s += v * ah[f];
            d += v * ah[OF + f];
        }
        s += __shfl_xor_sync(0xffffffffu, s, 1); s += __shfl_xor_sync(0xffffffffu, s, 2);
        d += __shfl_xor_sync(0xffffffffu, d, 1); d += __shfl_xor_sync(0xffffffffu, d, 2);
        if (qq == 0) {
            float e1 = expf(d), e2 = expf(0.2f * d);
            g_idat[h][n0 + row] = make_float4(s, expf(s), expf(0.2f * s), 0.f);
            g_jdat[h][n0 + row] = make_float4(d, e1, e2, 0.f);
            sE[0][row] = e1; sE[1][row] = e2;
        }
    }
    __syncthreads();

    char* tb = g_Vt + (size_t)(h * 64 + blockIdx.x) * VCH;
    for (int idx = t; idx < 64 * 32; idx += 256) {
        int k = idx >> 5, u = idx & 31;
        int c0 = u * 2;
        #pragma unroll
        for (int m = 0; m < 2; m++) {
            float e = sE[m][k];
            float v0 = e * sxt[k][c0], v1 = e * sxt[k][c0 + 1];
            __nv_bfloat16 h0 = __float2bfloat16(v0);
            __nv_bfloat16 h1 = __float2bfloat16(v1);
            float r0 = v0 - __bfloat162float(h0);
            float r1 = v1 - __bfloat162float(h1);
            __nv_bfloat16 l0 = __float2bfloat16(r0);
            __nv_bfloat16 l1 = __float2bfloat16(r1);
            uint32_t hv = (uint32_t)(*(unsigned short*)&h0) | ((uint32_t)(*(unsigned short*)&h1) << 16);
            uint32_t lv = (uint32_t)(*(unsigned short*)&l0) | ((uint32_t)(*(unsigned short*)&l1) << 16);
            *(uint32_t*)(tb + (2 * m) * SEGB + k * 144 + u * 4)     = hv;
            *(uint32_t*)(tb + (2 * m + 1) * SEGB + k * 144 + u * 4) = lv;
        }
    }
    // col 64: E hi in hi-seg, E lo in lo-seg (drives Z through the MMA)
    if (t < 64) {
        int k = t;
        #pragma unroll
        for (int m = 0; m < 2; m++) {
            float e = sE[m][k];
            __nv_bfloat16 hb = __float2bfloat16(e);
            float r = e - __bfloat162float(hb);
            __nv_bfloat16 lb = __float2bfloat16(r);
            *(__nv_bfloat16*)(tb + (2 * m) * SEGB + k * 144 + 128)     = hb;
            *(__nv_bfloat16*)(tb + (2 * m + 1) * SEGB + k * 144 + 128) = lb;
        }
    }
}

// ---------------------------------------------------------------------------
// Kernel 3 (main): 16 MMA warps (4 mg-groups x 4 ng) + 1 TMA warp.
// Group-local named barriers; P single-buffered (group-private rows);
// V double-buffered via dedicated TMA warp + 16-arrival vfree mbarrier.
// ---------------------------------------------------------------------------
#define SM_V   0                      // 2 x 36864 = 73728
#define SM_P1  73728                  // 128 x 144 = 18432
#define SM_P2  92160                  // 128 x 144
#define SM_Z   110592                 // 256 floats
#define SM_MB  111616                 // vfull[2], vfree[2]
#define SM_TOT 111648

__global__ __launch_bounds__(544, 1) void k_main(float* __restrict__ out) {
    extern __shared__ char smem[];
    const uint32_t sb = smem_u32(smem);
    const int h = blockIdx.y, i0 = blockIdx.x * 128;
    const int t = threadIdx.x, wid = t >> 5, lane = t & 31;
    const uint32_t vfull = sb + SM_MB;        // +0, +8
    const uint32_t vfree = sb + SM_MB + 16;   // +0, +8

    if (t == 0) {
        MBAR_INIT(vfull + 0, 1);  MBAR_INIT(vfull + 8, 1);
        MBAR_INIT(vfree + 0, 16); MBAR_INIT(vfree + 8, 16);
    }
    __syncthreads();

    const int mg = wid >> 2;
    const int ng = (wid + (wid >> 2)) & 3;   // diagonal remap: spread ng==3 over SMSPs
    const int q  = wid & 3;                  // j-quarter for stage A

    float d1[4][4] = {}, d2[4][4] = {}, dz1[2][4] = {}, dz2[2][4] = {};

    if (wid == 16) {
        // ----------------------------- TMA warp -----------------------------
        if (lane == 0) {
            #pragma unroll 1
            for (int m = 0; m < 64; m++) {
                const int b = m & 1;
                if (m >= 2) MBAR_WAIT(vfree + b * 8, ((m - 2) >> 1) & 1);
                asm volatile("mbarrier.arrive.expect_tx.shared.b64 _, [%0], %1;"
                             :: "r"(vfull + b * 8), "r"((uint32_t)VCH) : "memory");
                const char* src = g_Vt + (size_t)(h * 64 + m) * VCH;
                uint64_t sg; asm("cvta.to.global.u64 %0, %1;" : "=l"(sg) : "l"(src));
                asm volatile("cp.async.bulk.shared::cluster.global.mbarrier::complete_tx::bytes "
                             "[%0], [%1], %2, [%3];"
                             :: "r"(sb + SM_V + b * VCH), "l"(sg), "r"((uint32_t)VCH),
                                "r"(vfull + b * 8) : "memory");
            }
        }
    } else {
        // --------------------------- 16 MMA warps ---------------------------
        const int barid = 1 + mg;
        const int rowA = mg * 32 + lane;
        const float th = -g_idat[h][i0 + rowA].x;   // P1: dst >= -src

        const uint32_t a1b = sb + SM_P1 + (uint32_t)((mg * 32 + (lane & 15)) * 144 + (lane >> 4) * 16);
        const uint32_t a2b = a1b + (SM_P2 - SM_P1);
        const uint32_t bO  = (uint32_t)((lane & 15) * 144 + (lane >> 4) * 16 + ng * 32);
        const uint32_t bZ  = (uint32_t)((lane & 15) * 144 + 128);

        auto stageA = [&](int mc) {
            float jl = 0.f;
            if (lane < 16) jl = g_jdat[h][mc * 64 + q * 16 + lane].x;
            unsigned w = g_adjT[mc * 2 + (q >> 1)][i0 + rowA] >> ((q & 1) * 16);
            uint32_t v1[8], v2[8];
            #pragma unroll
            for (int p = 0; p < 8; p++) {
                float dd0 = __shfl_sync(0xffffffffu, jl, 2 * p);
                float dd1 = __shfl_sync(0xffffffffu, jl, 2 * p + 1);
                unsigned m0 = ((w >> (2 * p)) & 1u) ? 0x3F80u : 0u;
                unsigned m1 = ((w >> (2 * p + 1)) & 1u) ? 0x3F80u : 0u;
                unsigned x0 = (dd0 >= th) ? m0 : 0u;
                unsigned x1 = (dd1 >= th) ? m1 : 0u;
                v1[p] = x0 | (x1 << 16);
                v2[p] = (m0 ^ x0) | ((m1 ^ x1) << 16);
            }
            char* pr = smem + SM_P1 + rowA * 144 + q * 32;
            *(uint4*)(pr)      = make_uint4(v1[0], v1[1], v1[2], v1[3]);
            *(uint4*)(pr + 16) = make_uint4(v1[4], v1[5], v1[6], v1[7]);
            *(uint4*)(pr + (SM_P2 - SM_P1))      = make_uint4(v2[0], v2[1], v2[2], v2[3]);
            *(uint4*)(pr + (SM_P2 - SM_P1) + 16) = make_uint4(v2[4], v2[5], v2[6], v2[7]);
        };

        stageA(0);
        BAR_SYNC(barid, 128);

        #pragma unroll 1
        for (int m = 0; m < 64; m++) {
            const int b = m & 1;
            MBAR_WAIT(vfull + b * 8, (m >> 1) & 1);
            const uint32_t vb = sb + SM_V + b * VCH;
            #pragma unroll
            for (int ks = 0; ks < 4; ks++) {
                uint32_t a1f[2][4], a2f[2][4];
                LDSM_X4(a1f[0], a1b + ks * 32);
                LDSM_X4(a1f[1], a1b + 2304 + ks * 32);
                LDSM_X4(a2f[0], a2b + ks * 32);
                LDSM_X4(a2f[1], a2b + 2304 + ks * 32);
                const uint32_t kb = vb + (uint32_t)ks * 2304;
                uint32_t bf[4];
                LDSM_X4T(bf, kb + bO);                       // V1hi
                MMA(d1[0], a1f[0], bf[0], bf[1]); MMA(d1[1], a1f[0], bf[2], bf[3]);
                MMA(d1[2], a1f[1], bf[0], bf[1]); MMA(d1[3], a1f[1], bf[2], bf[3]);
                LDSM_X4T(bf, kb + SEGB + bO);                // V1lo
                MMA(d1[0], a1f[0], bf[0], bf[1]); MMA(d1[1], a1f[0], bf[2], bf[3]);
                MMA(d1[2], a1f[1], bf[0], bf[1]); MMA(d1[3], a1f[1], bf[2], bf[3]);
                LDSM_X4T(bf, kb + 2 * SEGB + bO);            // V2hi
                MMA(d2[0], a2f[0], bf[0], bf[1]); MMA(d2[1], a2f[0], bf[2], bf[3]);
                MMA(d2[2], a2f[1], bf[0], bf[1]); MMA(d2[3], a2f[1], bf[2], bf[3]);
                LDSM_X4T(bf, kb + 3 * SEGB + bO);            // V2lo
                MMA(d2[0], a2f[0], bf[0], bf[1]); MMA(d2[1], a2f[0], bf[2], bf[3]);
                MMA(d2[2], a2f[1], bf[0], bf[1]); MMA(d2[3], a2f[1], bf[2], bf[3]);
                if (ng == 3) {                               // Z columns (col 64)
                    uint32_t c2[2];
                    LDSM_X2T(c2, kb + bZ);
                    MMA(dz1[0], a1f[0], c2[0], c2[1]); MMA(dz1[1], a1f[1], c2[0], c2[1]);
                    LDSM_X2T(c2, kb + SEGB + bZ);
                    MMA(dz1[0], a1f[0], c2[0], c2[1]); MMA(dz1[1], a1f[1], c2[0], c2[1]);
                    LDSM_X2T(c2, kb + 2 * SEGB + bZ);
                    MMA(dz2[0], a2f[0], c2[0], c2[1]); MMA(dz2[1], a2f[1], c2[0], c2[1]);
                    LDSM_X2T(c2, kb + 3 * SEGB + bZ);
                    MMA(dz2[0], a2f[0], c2[0], c2[1]); MMA(dz2[1], a2f[1], c2[0], c2[1]);
                }
            }
            if (lane == 0) MBAR_ARRIVE(vfree + b * 8);
            BAR_SYNC(barid, 128);              // group's B(m) reads of P done
            if (m < 63) {
                stageA(m + 1);                 // overwrite own group's P rows
                BAR_SYNC(barid, 128);          // P ready for B(m+1)
            }
        }
    }

    __syncthreads();
    float* zs1 = (float*)(smem + SM_Z);
    float* zs2 = zs1 + 128;
    if (wid < 16 && ng == 3 && (lane & 3) == 0) {
        #pragma unroll
        for (int mt = 0; mt < 2; mt++) {
            int row = mg * 32 + mt * 16 + (lane >> 2);
            zs1[row]     = dz1[mt][0];
            zs1[row + 8] = dz1[mt][2];
            zs2[row]     = dz2[mt][0];
            zs2[row + 8] = dz2[mt][2];
        }
    }
    __syncthreads();
    if (wid < 16) {
        #pragma unroll
        for (int mt = 0; mt < 2; mt++) {
            int rlo = mg * 32 + mt * 16 + (lane >> 2);
            int rhi = rlo + 8;
            float4 ia = g_idat[h][i0 + rlo];
            float4 ib = g_idat[h][i0 + rhi];
            float zlo = 1.0f / (ia.y * zs1[rlo] + ia.z * zs2[rlo]);
            float zhi = 1.0f / (ib.y * zs1[rhi] + ib.z * zs2[rhi]);
            #pragma unroll
            for (int n8 = 0; n8 < 2; n8++) {
                int col = h * OF + ng * 16 + n8 * 8 + (lane & 3) * 2;
                float* q1 = d1[mt * 2 + n8];
                float* q2 = d2[mt * 2 + n8];
                float2 plo, phi;
                plo.x = (ia.y * q1[0] + ia.z * q2[0]) * zlo;
                plo.y = (ia.y * q1[1] + ia.z * q2[1]) * zlo;
                phi.x = (ib.y * q1[2] + ib.z * q2[2]) * zhi;
                phi.y = (ib.y * q1[3] + ib.z * q2[3]) * zhi;
                *(float2*)(out + (size_t)(i0 + rlo) * (NH * OF) + col) = plo;
                *(float2*)(out + (size_t)(i0 + rhi) * (NH * OF) + col) = phi;
            }
        }
    }
}

// ---------------------------------------------------------------------------
extern "C" void kernel_launch(void* const* d_in, const int* in_sizes, int n_in,
                              void* d_out, int out_size) {
    const float* x   = (const float*)d_in[0];  // [4096, 256]
    const float* W   = (const float*)d_in[1];  // [4, 256, 64]
    const float* a   = (const float*)d_in[2];  // [4, 128]
    const int*   adj = (const int*)d_in[3];    // [4096, 4096]
    float* out = (float*)d_out;                // [4096, 256]
    (void)in_sizes; (void)n_in; (void)out_size;

    cudaFuncSetAttribute(k_main, cudaFuncAttributeMaxDynamicSharedMemorySize, SM_TOT);

    k_bitpack<<<(NN * NN / 16) / 256, 256>>>(adj);
    k_xtv<<<dim3(NN / 64, NH), 256>>>(x, W, a);
    k_main<<<dim3(NN / 128, NH), 544, SM_TOT>>>(out);
}

// round 7
// speedup vs baseline: 2.2749x; 1.2710x over previous
#include <cuda_runtime.h>
#include <cuda_fp16.h>
#include <cstdint>

#define NN 4096
#define INF 256
#define OF 64
#define NH 4

// ---------------------------------------------------------------------------
// Scratch globals
// ---------------------------------------------------------------------------
__device__ float4   g_idat[NH][NN];        // {src, exp(src), exp(0.2*src), 0}
__device__ float4   g_jdat[NH][NN];        // {dst, exp(dst), exp(0.2*dst), 0}
__device__ unsigned g_adjT[NN / 32][NN];   // adjacency bits [wordcol][row]
// xt tiles: per (h,chunk): 2 segs (hi,lo), each [64 k][72 n] fp16, row=144B.
// cols 0-63 = xt (fp16 hi / residual lo); col 64 = 1.0 (hi) / 0.0 (lo) -> Z;
// cols 65-71 zero.
#define SEGB 9216
#define VCH  (2 * SEGB)
__device__ __align__(16) char g_Vt[NH * 64 * VCH];

// ---------------------------------------------------------------------------
// PTX helpers (family-generic: no tcgen05 on compute_103 virtual target)
// ---------------------------------------------------------------------------
__device__ __forceinline__ uint32_t smem_u32(const void* p) {
    uint32_t a;
    asm("{ .reg .u64 t; cvta.to.shared.u64 t, %1; cvt.u32.u64 %0, t; }" : "=r"(a) : "l"(p));
    return a;
}
#define MBAR_INIT(a, n) asm volatile("mbarrier.init.shared.b64 [%0], %1;" :: "r"(a), "r"(n) : "memory")
#define MBAR_WAIT(a, ph) do {                                                            \
    uint32_t _m = (a), _p = (ph), _d;                                                    \
    asm volatile("{ .reg .pred p; mbarrier.try_wait.parity.acquire.cta.shared::cta.b64 " \
                 "p, [%1], %2; selp.b32 %0, 1, 0, p; }" : "=r"(_d) : "r"(_m), "r"(_p) : "memory"); \
    if (!_d) {                                                                           \
        asm volatile("{ .reg .pred P1; WL_%=: mbarrier.try_wait.parity.acquire.cta.shared::cta.b64 " \
                     "P1, [%0], %1, 0x989680; @P1 bra.uni WD_%=; bra.uni WL_%=; WD_%=: }" \
                     :: "r"(_m), "r"(_p) : "memory");                                    \
    }                                                                                    \
} while (0)
#define MBAR_ARRIVE(a) asm volatile("mbarrier.arrive.shared.b64 _, [%0];" :: "r"(a) : "memory")
#define BAR_SYNC(id, n) asm volatile("bar.sync %0, %1;" :: "r"(id), "r"(n) : "memory")

#define LDSM_X4(r, a)                                                         \
    asm volatile("ldmatrix.sync.aligned.m8n8.x4.shared.b16 {%0,%1,%2,%3}, [%4];" \
        : "=r"((r)[0]), "=r"((r)[1]), "=r"((r)[2]), "=r"((r)[3]) : "r"(a))
#define LDSM_X4T(r, a)                                                        \
    asm volatile("ldmatrix.sync.aligned.m8n8.x4.trans.shared.b16 {%0,%1,%2,%3}, [%4];" \
        : "=r"((r)[0]), "=r"((r)[1]), "=r"((r)[2]), "=r"((r)[3]) : "r"(a))
#define LDSM_X2T(r, a)                                                        \
    asm volatile("ldmatrix.sync.aligned.m8n8.x2.trans.shared.b16 {%0,%1}, [%2];" \
        : "=r"((r)[0]), "=r"((r)[1]) : "r"(a))

#define MMA(d, a, b0_, b1_)                                                   \
    asm volatile("mma.sync.aligned.m16n8k16.row.col.f32.f16.f16.f32 "         \
        "{%0,%1,%2,%3},{%4,%5,%6,%7},{%8,%9},{%0,%1,%2,%3};"                  \
        : "+f"((d)[0]), "+f"((d)[1]), "+f"((d)[2]), "+f"((d)[3])              \
        : "r"((a)[0]), "r"((a)[1]), "r"((a)[2]), "r"((a)[3]), "r"(b0_), "r"(b1_))

// ---------------------------------------------------------------------------
// Kernel 1: adjacency bitpack (transposed), 1 word/thread, MLP=8
// ---------------------------------------------------------------------------
__global__ __launch_bounds__(256) void k_bitpack(const int* __restrict__ adj) {
    int w = blockIdx.x * 256 + threadIdx.x;   // word index
    int row = w >> 7, wc = w & 127;
    const int* p = adj + (size_t)row * NN + wc * 32;
    unsigned bits = 0;
    #pragma unroll
    for (int e = 0; e < 8; e++) {
        int4 v = *(const int4*)(p + e * 4);
        bits |= ((unsigned)(v.x > 0) << (e * 4)) | ((unsigned)(v.y > 0) << (e * 4 + 1)) |
                ((unsigned)(v.z > 0) << (e * 4 + 2)) | ((unsigned)(v.w > 0) << (e * 4 + 3));
    }
    g_adjT[wc][row] = bits;
}

// ---------------------------------------------------------------------------
// Kernel 2 (fused): xt GEMM + per-row scalars + fp16 hi/lo xt-tile build.
// ---------------------------------------------------------------------------
__global__ __launch_bounds__(256) void k_xtv(const float* __restrict__ x,
                                             const float* __restrict__ W,
                                             const float* __restrict__ a) {
    __shared__ float sx[16][68];
    __shared__ float sw[16][64];
    __shared__ float sxt[64][68];
    const int h = blockIdx.y, n0 = blockIdx.x * 64, t = threadIdx.x;
    const int tx = t & 15, ty = t >> 4;
    const float* Wh = W + h * INF * OF;

    float acc[4][4] = {};
    for (int k0 = 0; k0 < INF; k0 += 16) {
        const int n = t >> 2, kq = (t & 3) * 4;
        float4 xv = *(const float4*)(x + (n0 + n) * INF + k0 + kq);
        const int kk = t & 15, f4 = t >> 4;
        float4 wv = *(const float4*)(Wh + (kk + k0) * OF + f4 * 4);
        __syncthreads();
        sx[kq + 0][n] = xv.x; sx[kq + 1][n] = xv.y;
        sx[kq + 2][n] = xv.z; sx[kq + 3][n] = xv.w;
        *(float4*)&sw[kk][f4 * 4] = wv;
        __syncthreads();
        #pragma unroll
        for (int k = 0; k < 16; k++) {
            float4 av = *(float4*)&sx[k][ty * 4];
            float4 bv = *(float4*)&sw[k][tx * 4];
            acc[0][0] += av.x * bv.x; acc[0][1] += av.x * bv.y; acc[0][2] += av.x * bv.z; acc[0][3] += av.x * bv.w;
            acc[1][0] += av.y * bv.x; acc[1][1] += av.y * bv.y; acc[1][2] += av.y * bv.z; acc[1][3] += av.y * bv.w;
            acc[2][0] += av.z * bv.x; acc[2][1] += av.z * bv.y; acc[2][2] += av.z * bv.z; acc[2][3] += av.z * bv.w;
            acc[3][0] += av.w * bv.x; acc[3][1] += av.w * bv.y; acc[3][2] += av.w * bv.z; acc[3][3] += av.w * bv.w;
        }
    }
    __syncthreads();
    #pragma unroll
    for (int r = 0; r < 4; r++)
        *(float4*)&sxt[ty * 4 + r][tx * 4] = make_float4(acc[r][0], acc[r][1], acc[r][2], acc[r][3]);
    __syncthreads();

    // per-row src/dst dots
    {
        const int row = t >> 2, qq = t & 3;
        const float* ah = a + h * 2 * OF;
        float s = 0.f, d = 0.f;
        #pragma unroll
        for (int ff = 0; ff < 16; ff++) {
            int f = qq * 16 + ff;
            float v = sxt[row][f];
            s += v * ah[f];
            d += v * ah[OF + f];
        }
        s += __shfl_xor_sync(0xffffffffu, s, 1); s += __shfl_xor_sync(0xffffffffu, s, 2);
        d += __shfl_xor_sync(0xffffffffu, d, 1); d += __shfl_xor_sync(0xffffffffu, d, 2);
        if (qq == 0) {
            g_idat[h][n0 + row] = make_float4(s, expf(s), expf(0.2f * s), 0.f);
            g_jdat[h][n0 + row] = make_float4(d, expf(d), expf(0.2f * d), 0.f);
        }
    }
    __syncthreads();

    // xt tiles: fp16 hi / residual lo; col 64 = 1/0 (Z column); 65-71 zero
    char* tb = g_Vt + (size_t)(h * 64 + blockIdx.x) * VCH;
    for (int idx = t; idx < 64 * 36; idx += 256) {
        int k = idx / 36, u = idx % 36;
        int c0 = u * 2;
        float v0, v1;
        if (c0 < 64)       { v0 = sxt[k][c0]; v1 = sxt[k][c0 + 1]; }
        else if (c0 == 64) { v0 = 1.0f;       v1 = 0.0f; }
        else               { v0 = 0.0f;       v1 = 0.0f; }
        __half h0 = __float2half_rn(v0), h1 = __float2half_rn(v1);
        __half l0 = __float2half_rn(v0 - __half2float(h0));
        __half l1 = __float2half_rn(v1 - __half2float(h1));
        uint32_t hv = (uint32_t)(*(unsigned short*)&h0) | ((uint32_t)(*(unsigned short*)&h1) << 16);
        uint32_t lv = (uint32_t)(*(unsigned short*)&l0) | ((uint32_t)(*(unsigned short*)&l1) << 16);
        *(uint32_t*)(tb + k * 144 + u * 4)        = hv;
        *(uint32_t*)(tb + SEGB + k * 144 + u * 4) = lv;
    }
}

// ---------------------------------------------------------------------------
// Kernel 3 (main): W (fp16 full-weight matrix) @ xt(hi+lo). 16 MMA warps
// (4 mg x 4 ng) + 1 TMA warp. W group-private single-buffered; xt tiles
// double-buffered via TMA warp.
// ---------------------------------------------------------------------------
#define SM_V   0                      // 2 x 18432 = 36864
#define SM_W   36864                  // 128 x 144 = 18432
#define SM_Z   55296                  // 128 floats
#define SM_MB  55808                  // vfull[2], vfree[2]
#define SM_TOT 55840

__global__ __launch_bounds__(544, 1) void k_main(float* __restrict__ out) {
    extern __shared__ char smem[];
    const uint32_t sb = smem_u32(smem);
    const int h = blockIdx.y, i0 = blockIdx.x * 128;
    const int t = threadIdx.x, wid = t >> 5, lane = t & 31;
    const uint32_t vfull = sb + SM_MB;        // +0, +8
    const uint32_t vfree = sb + SM_MB + 16;   // +0, +8

    if (t == 0) {
        MBAR_INIT(vfull + 0, 1);  MBAR_INIT(vfull + 8, 1);
        MBAR_INIT(vfree + 0, 16); MBAR_INIT(vfree + 8, 16);
    }
    __syncthreads();

    const int mg = wid >> 2;
    const int ng = (wid + (wid >> 2)) & 3;   // diagonal remap of ng over SMSPs
    const int q  = wid & 3;                  // j-quarter for stage A

    float d[4][4] = {}, dz[2][4] = {};

    if (wid == 16) {
        // ----------------------------- TMA warp -----------------------------
        if (lane == 0) {
            #pragma unroll 1
            for (int m = 0; m < 64; m++) {
                const int b = m & 1;
                if (m >= 2) MBAR_WAIT(vfree + b * 8, ((m - 2) >> 1) & 1);
                asm volatile("mbarrier.arrive.expect_tx.shared.b64 _, [%0], %1;"
                             :: "r"(vfull + b * 8), "r"((uint32_t)VCH) : "memory");
                const char* src = g_Vt + (size_t)(h * 64 + m) * VCH;
                uint64_t sg; asm("cvta.to.global.u64 %0, %1;" : "=l"(sg) : "l"(src));
                asm volatile("cp.async.bulk.shared::cluster.global.mbarrier::complete_tx::bytes "
                             "[%0], [%1], %2, [%3];"
                             :: "r"(sb + SM_V + b * VCH), "l"(sg), "r"((uint32_t)VCH),
                                "r"(vfull + b * 8) : "memory");
            }
        }
    } else {
        // --------------------------- 16 MMA warps ---------------------------
        const int barid = 1 + mg;
        const int rowA = mg * 32 + lane;
        const float4 id = g_idat[h][i0 + rowA];
        const float th = -id.x, A1 = id.y, A2 = id.z;   // branch 1: dst >= -src

        const uint32_t aW = sb + SM_W + (uint32_t)((mg * 32 + (lane & 15)) * 144 + (lane >> 4) * 16);
        const uint32_t bO = (uint32_t)((lane & 15) * 144 + (lane >> 4) * 16 + ng * 32);
        const uint32_t bZ = (uint32_t)((lane & 15) * 144 + 128);

        // stage A: build 16-j strip of the fp16 weight matrix W for this group
        auto stageA = [&](int mc) {
            float4 jd = make_float4(0.f, 0.f, 0.f, 0.f);
            if (lane < 16) jd = g_jdat[h][mc * 64 + q * 16 + lane];
            unsigned w = g_adjT[mc * 2 + (q >> 1)][i0 + rowA] >> ((q & 1) * 16);
            uint32_t vv[8];
            #pragma unroll
            for (int p = 0; p < 8; p++) {
                float dd0 = __shfl_sync(0xffffffffu, jd.x, 2 * p);
                float e10 = __shfl_sync(0xffffffffu, jd.y, 2 * p);
                float e20 = __shfl_sync(0xffffffffu, jd.z, 2 * p);
                float dd1 = __shfl_sync(0xffffffffu, jd.x, 2 * p + 1);
                float e11 = __shfl_sync(0xffffffffu, jd.y, 2 * p + 1);
                float e21 = __shfl_sync(0xffffffffu, jd.z, 2 * p + 1);
                float w0 = (dd0 >= th) ? A1 * e10 : A2 * e20;
                float w1 = (dd1 >= th) ? A1 * e11 : A2 * e21;
                w0 = ((w >> (2 * p)) & 1u) ? w0 : 0.f;
                w1 = ((w >> (2 * p + 1)) & 1u) ? w1 : 0.f;
                __half2 packed = __floats2half2_rn(w0, w1);
                vv[p] = *(uint32_t*)&packed;
            }
            char* pr = smem + SM_W + rowA * 144 + q * 32;
            *(uint4*)(pr)      = make_uint4(vv[0], vv[1], vv[2], vv[3]);
            *(uint4*)(pr + 16) = make_uint4(vv[4], vv[5], vv[6], vv[7]);
        };

        stageA(0);
        BAR_SYNC(barid, 128);

        #pragma unroll 1
        for (int m = 0; m < 64; m++) {
            const int b = m & 1;
            MBAR_WAIT(vfull + b * 8, (m >> 1) & 1);
            const uint32_t vb = sb + SM_V + b * VCH;
            #pragma unroll
            for (int ks = 0; ks < 4; ks++) {
                uint32_t af[2][4];
                LDSM_X4(af[0], aW + ks * 32);
                LDSM_X4(af[1], aW + 2304 + ks * 32);
                const uint32_t kb = vb + (uint32_t)ks * 2304;
                uint32_t bf[4];
                LDSM_X4T(bf, kb + bO);               // xt hi
                MMA(d[0], af[0], bf[0], bf[1]); MMA(d[1], af[0], bf[2], bf[3]);
                MMA(d[2], af[1], bf[0], bf[1]); MMA(d[3], af[1], bf[2], bf[3]);
                LDSM_X4T(bf, kb + SEGB + bO);        // xt lo (same accumulators)
                MMA(d[0], af[0], bf[0], bf[1]); MMA(d[1], af[0], bf[2], bf[3]);
                MMA(d[2], af[1], bf[0], bf[1]); MMA(d[3], af[1], bf[2], bf[3]);
                if (ng == 3) {                       // Z: ones column (hi seg only)
                    uint32_t c2[2];
                    LDSM_X2T(c2, kb + bZ);
                    MMA(dz[0], af[0], c2[0], c2[1]);
                    MMA(dz[1], af[1], c2[0], c2[1]);
                }
            }
            if (lane == 0) MBAR_ARRIVE(vfree + b * 8);
            BAR_SYNC(barid, 128);              // group's B(m) reads of W done
            if (m < 63) {
                stageA(m + 1);
                BAR_SYNC(barid, 128);          // W ready for B(m+1)
            }
        }
    }

    __syncthreads();
    float* zs = (float*)(smem + SM_Z);
    if (wid < 16 && ng == 3 && (lane & 3) == 0) {
        #pragma unroll
        for (int mt = 0; mt < 2; mt++) {
            int row = mg * 32 + mt * 16 + (lane >> 2);
            zs[row]     = dz[mt][0];
            zs[row + 8] = dz[mt][2];
        }
    }
    __syncthreads();
    if (wid < 16) {
        #pragma unroll
        for (int mt = 0; mt < 2; mt++) {
            int rlo = mg * 32 + mt * 16 + (lane >> 2);
            int rhi = rlo + 8;
            float zlo = 1.0f / zs[rlo];
            float zhi = 1.0f / zs[rhi];
            #pragma unroll
            for (int n8 = 0; n8 < 2; n8++) {
                int col = h * OF + ng * 16 + n8 * 8 + (lane & 3) * 2;
                float* dd = d[mt * 2 + n8];
                float2 plo = make_float2(dd[0] * zlo, dd[1] * zlo);
                float2 phi = make_float2(dd[2] * zhi, dd[3] * zhi);
                *(float2*)(out + (size_t)(i0 + rlo) * (NH * OF) + col) = plo;
                *(float2*)(out + (size_t)(i0 + rhi) * (NH * OF) + col) = phi;
            }
        }
    }
}

// ---------------------------------------------------------------------------
extern "C" void kernel_launch(void* const* d_in, const int* in_sizes, int n_in,
                              void* d_out, int out_size) {
    const float* x   = (const float*)d_in[0];  // [4096, 256]
    const float* W   = (const float*)d_in[1];  // [4, 256, 64]
    const float* a   = (const float*)d_in[2];  // [4, 128]
    const int*   adj = (const int*)d_in[3];    // [4096, 4096]
    float* out = (float*)d_out;                // [4096, 256]
    (void)in_sizes; (void)n_in; (void)out_size;

    cudaFuncSetAttribute(k_main, cudaFuncAttributeMaxDynamicSharedMemorySize, SM_TOT);

    k_bitpack<<<(NN * NN / 32) / 256, 256>>>(adj);
    k_xtv<<<dim3(NN / 64, NH), 256>>>(x, W, a);
    k_main<<<dim3(NN / 128, NH), 544, SM_TOT>>>(out);
}

// round 8
// speedup vs baseline: 2.6284x; 1.1554x over previous
#include <cuda_runtime.h>
#include <cuda_fp16.h>
#include <cstdint>

#define NN 4096
#define INF 256
#define OF 64
#define NH 4

// ---------------------------------------------------------------------------
// Scratch globals
// ---------------------------------------------------------------------------
__device__ float4   g_idat[NH][NN];        // {src, exp(src), exp(0.2*src), 0}
__device__ float4   g_jdat[NH][NN];        // {dst, exp(dst), exp(0.2*dst), 0}
__device__ unsigned g_adjT[NN / 32][NN];   // adjacency bits [wordcol][row]
// xt tiles: per (h,chunk): ONE fp16 seg [64 k][72 n], row=144B.
// cols 0-63 = xt (fp16); col 64 = 1.0 -> Z column; cols 65-71 zero.
#define SEGB 9216
#define VCH  SEGB
__device__ __align__(16) char g_Vt[NH * 64 * VCH];

// ---------------------------------------------------------------------------
// PTX helpers (family-generic: no tcgen05 on compute_103 virtual target)
// ---------------------------------------------------------------------------
__device__ __forceinline__ uint32_t smem_u32(const void* p) {
    uint32_t a;
    asm("{ .reg .u64 t; cvta.to.shared.u64 t, %1; cvt.u32.u64 %0, t; }" : "=r"(a) : "l"(p));
    return a;
}
#define MBAR_INIT(a, n) asm volatile("mbarrier.init.shared.b64 [%0], %1;" :: "r"(a), "r"(n) : "memory")
#define MBAR_WAIT(a, ph) do {                                                            \
    uint32_t _m = (a), _p = (ph), _d;                                                    \
    asm volatile("{ .reg .pred p; mbarrier.try_wait.parity.acquire.cta.shared::cta.b64 " \
                 "p, [%1], %2; selp.b32 %0, 1, 0, p; }" : "=r"(_d) : "r"(_m), "r"(_p) : "memory"); \
    if (!_d) {                                                                           \
        asm volatile("{ .reg .pred P1; WL_%=: mbarrier.try_wait.parity.acquire.cta.shared::cta.b64 " \
                     "P1, [%0], %1, 0x989680; @P1 bra.uni WD_%=; bra.uni WL_%=; WD_%=: }" \
                     :: "r"(_m), "r"(_p) : "memory");                                    \
    }                                                                                    \
} while (0)
#define MBAR_ARRIVE(a) asm volatile("mbarrier.arrive.shared.b64 _, [%0];" :: "r"(a) : "memory")
#define BAR_SYNC(id, n) asm volatile("bar.sync %0, %1;" :: "r"(id), "r"(n) : "memory")

#define LDSM_X4(r, a)                                                         \
    asm volatile("ldmatrix.sync.aligned.m8n8.x4.shared.b16 {%0,%1,%2,%3}, [%4];" \
        : "=r"((r)[0]), "=r"((r)[1]), "=r"((r)[2]), "=r"((r)[3]) : "r"(a))
#define LDSM_X4T(r, a)                                                        \
    asm volatile("ldmatrix.sync.aligned.m8n8.x4.trans.shared.b16 {%0,%1,%2,%3}, [%4];" \
        : "=r"((r)[0]), "=r"((r)[1]), "=r"((r)[2]), "=r"((r)[3]) : "r"(a))
#define LDSM_X2T(r, a)                                                        \
    asm volatile("ldmatrix.sync.aligned.m8n8.x2.trans.shared.b16 {%0,%1}, [%2];" \
        : "=r"((r)[0]), "=r"((r)[1]) : "r"(a))

#define MMA(d, a, b0_, b1_)                                                   \
    asm volatile("mma.sync.aligned.m16n8k16.row.col.f32.f16.f16.f32 "         \
        "{%0,%1,%2,%3},{%4,%5,%6,%7},{%8,%9},{%0,%1,%2,%3};"                  \
        : "+f"((d)[0]), "+f"((d)[1]), "+f"((d)[2]), "+f"((d)[3])              \
        : "r"((a)[0]), "r"((a)[1]), "r"((a)[2]), "r"((a)[3]), "r"(b0_), "r"(b1_))

// ---------------------------------------------------------------------------
// Kernel 1: adjacency bitpack (transposed), 16 elements/thread (round-6 best)
// ---------------------------------------------------------------------------
__global__ __launch_bounds__(256) void k_bitpack(const int* __restrict__ adj) {
    size_t tid = (size_t)blockIdx.x * 256 + threadIdx.x;
    int lane = threadIdx.x & 31;
    size_t base = tid * 16;
    int row = (int)(base >> 12), col = (int)(base & 4095);
    unsigned bits = 0;
    #pragma unroll
    for (int e = 0; e < 4; e++) {
        int4 v = *(const int4*)(adj + (size_t)row * NN + col + e * 4);
        bits |= ((unsigned)(v.x > 0) << (e * 4)) | ((unsigned)(v.y > 0) << (e * 4 + 1)) |
                ((unsigned)(v.z > 0) << (e * 4 + 2)) | ((unsigned)(v.w > 0) << (e * 4 + 3));
    }
    unsigned val = bits << (((unsigned)(col >> 4) & 1u) * 16u);
    val |= __shfl_xor_sync(0xffffffffu, val, 1);
    if ((lane & 1) == 0) g_adjT[col >> 5][row] = val;
}

// ---------------------------------------------------------------------------
// Kernel 2 (fused): xt GEMM + per-row scalars + fp16 xt-tile build.
// ---------------------------------------------------------------------------
__global__ __launch_bounds__(256) void k_xtv(const float* __restrict__ x,
                                             const float* __restrict__ W,
                                             const float* __restrict__ a) {
    __shared__ float sx[16][68];
    __shared__ float sw[16][64];
    __shared__ float sxt[64][68];
    const int h = blockIdx.y, n0 = blockIdx.x * 64, t = threadIdx.x;
    const int tx = t & 15, ty = t >> 4;
    const float* Wh = W + h * INF * OF;

    float acc[4][4] = {};
    for (int k0 = 0; k0 < INF; k0 += 16) {
        const int n = t >> 2, kq = (t & 3) * 4;
        float4 xv = *(const float4*)(x + (n0 + n) * INF + k0 + kq);
        const int kk = t & 15, f4 = t >> 4;
        float4 wv = *(const float4*)(Wh + (kk + k0) * OF + f4 * 4);
        __syncthreads();
        sx[kq + 0][n] = xv.x; sx[kq + 1][n] = xv.y;
        sx[kq + 2][n] = xv.z; sx[kq + 3][n] = xv.w;
        *(float4*)&sw[kk][f4 * 4] = wv;
        __syncthreads();
        #pragma unroll
        for (int k = 0; k < 16; k++) {
            float4 av = *(float4*)&sx[k][ty * 4];
            float4 bv = *(float4*)&sw[k][tx * 4];
            acc[0][0] += av.x * bv.x; acc[0][1] += av.x * bv.y; acc[0][2] += av.x * bv.z; acc[0][3] += av.x * bv.w;
            acc[1][0] += av.y * bv.x; acc[1][1] += av.y * bv.y; acc[1][2] += av.y * bv.z; acc[1][3] += av.y * bv.w;
            acc[2][0] += av.z * bv.x; acc[2][1] += av.z * bv.y; acc[2][2] += av.z * bv.z; acc[2][3] += av.z * bv.w;
            acc[3][0] += av.w * bv.x; acc[3][1] += av.w * bv.y; acc[3][2] += av.w * bv.z; acc[3][3] += av.w * bv.w;
        }
    }
    __syncthreads();
    #pragma unroll
    for (int r = 0; r < 4; r++)
        *(float4*)&sxt[ty * 4 + r][tx * 4] = make_float4(acc[r][0], acc[r][1], acc[r][2], acc[r][3]);
    __syncthreads();

    // per-row src/dst dots
    {
        const int row = t >> 2, qq = t & 3;
        const float* ah = a + h * 2 * OF;
        float s = 0.f, d = 0.f;
        #pragma unroll
        for (int ff = 0; ff < 16; ff++) {
            int f = qq * 16 + ff;
            float v = sxt[row][f];
            s += v * ah[f];
            d += v * ah[OF + f];
        }
        s += __shfl_xor_sync(0xffffffffu, s, 1); s += __shfl_xor_sync(0xffffffffu, s, 2);
        d += __shfl_xor_sync(0xffffffffu, d, 1); d += __shfl_xor_sync(0xffffffffu, d, 2);
        if (qq == 0) {
            g_idat[h][n0 + row] = make_float4(s, expf(s), expf(0.2f * s), 0.f);
            g_jdat[h][n0 + row] = make_float4(d, expf(d), expf(0.2f * d), 0.f);
        }
    }
    __syncthreads();

    // xt tile: fp16; col 64 = 1.0 (Z column); cols 65-71 zero
    char* tb = g_Vt + (size_t)(h * 64 + blockIdx.x) * VCH;
    for (int idx = t; idx < 64 * 36; idx += 256) {
        int k = idx / 36, u = idx % 36;
        int c0 = u * 2;
        float v0, v1;
        if (c0 < 64)       { v0 = sxt[k][c0]; v1 = sxt[k][c0 + 1]; }
        else if (c0 == 64) { v0 = 1.0f;       v1 = 0.0f; }
        else               { v0 = 0.0f;       v1 = 0.0f; }
        __half2 hp = __floats2half2_rn(v0, v1);
        *(uint32_t*)(tb + k * 144 + u * 4) = *(uint32_t*)&hp;
    }
}

// ---------------------------------------------------------------------------
// Kernel 3 (main): W (fp16 full-weight matrix) @ [xt | 1]. 16 MMA warps
// (4 mg x 4 ng) + 1 TMA warp. W group-private single-buffered; xt tiles
// double-buffered via TMA warp.
// ---------------------------------------------------------------------------
#define SM_V   0                      // 2 x 9216 = 18432
#define SM_W   18432                  // 128 x 144 = 18432
#define SM_Z   36864                  // 128 floats
#define SM_MB  37376                  // vfull[2], vfree[2]
#define SM_TOT 37408

__global__ __launch_bounds__(544, 1) void k_main(float* __restrict__ out) {
    extern __shared__ char smem[];
    const uint32_t sb = smem_u32(smem);
    const int h = blockIdx.y, i0 = blockIdx.x * 128;
    const int t = threadIdx.x, wid = t >> 5, lane = t & 31;
    const uint32_t vfull = sb + SM_MB;        // +0, +8
    const uint32_t vfree = sb + SM_MB + 16;   // +0, +8

    if (t == 0) {
        MBAR_INIT(vfull + 0, 1);  MBAR_INIT(vfull + 8, 1);
        MBAR_INIT(vfree + 0, 16); MBAR_INIT(vfree + 8, 16);
    }
    __syncthreads();

    const int mg = wid >> 2;
    const int ng = (wid + (wid >> 2)) & 3;   // diagonal remap of ng over SMSPs
    const int q  = wid & 3;                  // j-quarter for stage A

    float d[4][4] = {}, dz[2][4] = {};

    if (wid == 16) {
        // ----------------------------- TMA warp -----------------------------
        if (lane == 0) {
            #pragma unroll 1
            for (int m = 0; m < 64; m++) {
                const int b = m & 1;
                if (m >= 2) MBAR_WAIT(vfree + b * 8, ((m - 2) >> 1) & 1);
                asm volatile("mbarrier.arrive.expect_tx.shared.b64 _, [%0], %1;"
                             :: "r"(vfull + b * 8), "r"((uint32_t)VCH) : "memory");
                const char* src = g_Vt + (size_t)(h * 64 + m) * VCH;
                uint64_t sg; asm("cvta.to.global.u64 %0, %1;" : "=l"(sg) : "l"(src));
                asm volatile("cp.async.bulk.shared::cluster.global.mbarrier::complete_tx::bytes "
                             "[%0], [%1], %2, [%3];"
                             :: "r"(sb + SM_V + b * VCH), "l"(sg), "r"((uint32_t)VCH),
                                "r"(vfull + b * 8) : "memory");
            }
        }
    } else {
        // --------------------------- 16 MMA warps ---------------------------
        const int barid = 1 + mg;
        const int rowA = mg * 32 + lane;
        const float4 id = g_idat[h][i0 + rowA];
        const float th = -id.x, A1 = id.y, A2 = id.z;   // branch 1: dst >= -src

        const uint32_t aW = sb + SM_W + (uint32_t)((mg * 32 + (lane & 15)) * 144 + (lane >> 4) * 16);
        const uint32_t bO = (uint32_t)((lane & 15) * 144 + (lane >> 4) * 16 + ng * 32);
        const uint32_t bZ = (uint32_t)((lane & 15) * 144 + 128);

        // stage A: build 16-j strip of the fp16 weight matrix W for this group
        auto stageA = [&](int mc) {
            float4 jd = make_float4(0.f, 0.f, 0.f, 0.f);
            if (lane < 16) jd = g_jdat[h][mc * 64 + q * 16 + lane];
            unsigned w = g_adjT[mc * 2 + (q >> 1)][i0 + rowA] >> ((q & 1) * 16);
            uint32_t vv[8];
            #pragma unroll
            for (int p = 0; p < 8; p++) {
                float dd0 = __shfl_sync(0xffffffffu, jd.x, 2 * p);
                float e10 = __shfl_sync(0xffffffffu, jd.y, 2 * p);
                float e20 = __shfl_sync(0xffffffffu, jd.z, 2 * p);
                float dd1 = __shfl_sync(0xffffffffu, jd.x, 2 * p + 1);
                float e11 = __shfl_sync(0xffffffffu, jd.y, 2 * p + 1);
                float e21 = __shfl_sync(0xffffffffu, jd.z, 2 * p + 1);
                float w0 = (dd0 >= th) ? A1 * e10 : A2 * e20;
                float w1 = (dd1 >= th) ? A1 * e11 : A2 * e21;
                w0 = ((w >> (2 * p)) & 1u) ? w0 : 0.f;
                w1 = ((w >> (2 * p + 1)) & 1u) ? w1 : 0.f;
                __half2 packed = __floats2half2_rn(w0, w1);
                vv[p] = *(uint32_t*)&packed;
            }
            char* pr = smem + SM_W + rowA * 144 + q * 32;
            *(uint4*)(pr)      = make_uint4(vv[0], vv[1], vv[2], vv[3]);
            *(uint4*)(pr + 16) = make_uint4(vv[4], vv[5], vv[6], vv[7]);
        };

        stageA(0);
        BAR_SYNC(barid, 128);

        #pragma unroll 1
        for (int m = 0; m < 64; m++) {
            const int b = m & 1;
            MBAR_WAIT(vfull + b * 8, (m >> 1) & 1);
            const uint32_t vb = sb + SM_V + b * VCH;
            #pragma unroll
            for (int ks = 0; ks < 4; ks++) {
                uint32_t af[2][4];
                LDSM_X4(af[0], aW + ks * 32);
                LDSM_X4(af[1], aW + 2304 + ks * 32);
                const uint32_t kb = vb + (uint32_t)ks * 2304;
                uint32_t bf[4];
                LDSM_X4T(bf, kb + bO);               // xt (fp16)
                MMA(d[0], af[0], bf[0], bf[1]); MMA(d[1], af[0], bf[2], bf[3]);
                MMA(d[2], af[1], bf[0], bf[1]); MMA(d[3], af[1], bf[2], bf[3]);
                if (ng == 3) {                       // Z: ones column
                    uint32_t c2[2];
                    LDSM_X2T(c2, kb + bZ);
                    MMA(dz[0], af[0], c2[0], c2[1]);
                    MMA(dz[1], af[1], c2[0], c2[1]);
                }
            }
            if (lane == 0) MBAR_ARRIVE(vfree + b * 8);
            BAR_SYNC(barid, 128);              // group's B(m) reads of W done
            if (m < 63) {
                stageA(m + 1);
                BAR_SYNC(barid, 128);          // W ready for B(m+1)
            }
        }
    }

    __syncthreads();
    float* zs = (float*)(smem + SM_Z);
    if (wid < 16 && ng == 3 && (lane & 3) == 0) {
        #pragma unroll
        for (int mt = 0; mt < 2; mt++) {
            int row = mg * 32 + mt * 16 + (lane >> 2);
            zs[row]     = dz[mt][0];
            zs[row + 8] = dz[mt][2];
        }
    }
    __syncthreads();
    if (wid < 16) {
        #pragma unroll
        for (int mt = 0; mt < 2; mt++) {
            int rlo = mg * 32 + mt * 16 + (lane >> 2);
            int rhi = rlo + 8;
            float zlo = 1.0f / zs[rlo];
            float zhi = 1.0f / zs[rhi];
            #pragma unroll
            for (int n8 = 0; n8 < 2; n8++) {
                int col = h * OF + ng * 16 + n8 * 8 + (lane & 3) * 2;
                float* dd = d[mt * 2 + n8];
                float2 plo = make_float2(dd[0] * zlo, dd[1] * zlo);
                float2 phi = make_float2(dd[2] * zhi, dd[3] * zhi);
                *(float2*)(out + (size_t)(i0 + rlo) * (NH * OF) + col) = plo;
                *(float2*)(out + (size_t)(i0 + rhi) * (NH * OF) + col) = phi;
            }
        }
    }
}

// ---------------------------------------------------------------------------
extern "C" void kernel_launch(void* const* d_in, const int* in_sizes, int n_in,
                              void* d_out, int out_size) {
    const float* x   = (const float*)d_in[0];  // [4096, 256]
    const float* W   = (const float*)d_in[1];  // [4, 256, 64]
    const float* a   = (const float*)d_in[2];  // [4, 128]
    const int*   adj = (const int*)d_in[3];    // [4096, 4096]
    float* out = (float*)d_out;                // [4096, 256]
    (void)in_sizes; (void)n_in; (void)out_size;

    cudaFuncSetAttribute(k_main, cudaFuncAttributeMaxDynamicSharedMemorySize, SM_TOT);

    k_bitpack<<<(NN * NN / 16) / 256, 256>>>(adj);
    k_xtv<<<dim3(NN / 64, NH), 256>>>(x, W, a);
    k_main<<<dim3(NN / 128, NH), 544, SM_TOT>>>(out);
}

// round 9
// speedup vs baseline: 3.2002x; 1.2175x over previous
#include <cuda_runtime.h>
#include <cuda_fp16.h>
#include <cstdint>

#define NN 4096
#define INF 256
#define OF 64
#define NH 4

// ---------------------------------------------------------------------------
// Scratch globals
// ---------------------------------------------------------------------------
__device__ float4   g_idat[NH][NN];        // {src, exp(src), exp(0.2*src), 0}
__device__ unsigned g_adjT[NN / 32][NN];   // adjacency bits [wordcol][row]
// xt tiles: per (h,chunk): fp16 seg [64 k][72 n] (rows 144B) + 1KB tail:
//   [9216,9472) dst f32[64]   [9472,9728) e1 f32[64]   [9728,9984) e2 f32[64]
// cols 0-63 = xt (fp16); col 64 = 1.0 -> Z column; cols 65-71 zero.
#define SEGB 9216
#define VCH  10240
__device__ __align__(16) char g_Vt[NH * 64 * VCH];

// ---------------------------------------------------------------------------
// PTX helpers (family-generic: no tcgen05 on compute_103 virtual target)
// ---------------------------------------------------------------------------
__device__ __forceinline__ uint32_t smem_u32(const void* p) {
    uint32_t a;
    asm("{ .reg .u64 t; cvta.to.shared.u64 t, %1; cvt.u32.u64 %0, t; }" : "=r"(a) : "l"(p));
    return a;
}
#define MBAR_INIT(a, n) asm volatile("mbarrier.init.shared.b64 [%0], %1;" :: "r"(a), "r"(n) : "memory")
#define MBAR_WAIT(a, ph) do {                                                            \
    uint32_t _m = (a), _p = (ph), _d;                                                    \
    asm volatile("{ .reg .pred p; mbarrier.try_wait.parity.acquire.cta.shared::cta.b64 " \
                 "p, [%1], %2; selp.b32 %0, 1, 0, p; }" : "=r"(_d) : "r"(_m), "r"(_p) : "memory"); \
    if (!_d) {                                                                           \
        asm volatile("{ .reg .pred P1; WL_%=: mbarrier.try_wait.parity.acquire.cta.shared::cta.b64 " \
                     "P1, [%0], %1, 0x989680; @P1 bra.uni WD_%=; bra.uni WL_%=; WD_%=: }" \
                     :: "r"(_m), "r"(_p) : "memory");                                    \
    }                                                                                    \
} while (0)
#define MBAR_ARRIVE(a) asm volatile("mbarrier.arrive.shared.b64 _, [%0];" :: "r"(a) : "memory")
#define BAR_SYNC(id, n) asm volatile("bar.sync %0, %1;" :: "r"(id), "r"(n) : "memory")

#define LDSM_X4(r, a)                                                         \
    asm volatile("ldmatrix.sync.aligned.m8n8.x4.shared.b16 {%0,%1,%2,%3}, [%4];" \
        : "=r"((r)[0]), "=r"((r)[1]), "=r"((r)[2]), "=r"((r)[3]) : "r"(a))
#define LDSM_X4T(r, a)                                                        \
    asm volatile("ldmatrix.sync.aligned.m8n8.x4.trans.shared.b16 {%0,%1,%2,%3}, [%4];" \
        : "=r"((r)[0]), "=r"((r)[1]), "=r"((r)[2]), "=r"((r)[3]) : "r"(a))
#define LDSM_X2T(r, a)                                                        \
    asm volatile("ldmatrix.sync.aligned.m8n8.x2.trans.shared.b16 {%0,%1}, [%2];" \
        : "=r"((r)[0]), "=r"((r)[1]) : "r"(a))

#define MMA(d, a, b0_, b1_)                                                   \
    asm volatile("mma.sync.aligned.m16n8k16.row.col.f32.f16.f16.f32 "         \
        "{%0,%1,%2,%3},{%4,%5,%6,%7},{%8,%9},{%0,%1,%2,%3};"                  \
        : "+f"((d)[0]), "+f"((d)[1]), "+f"((d)[2]), "+f"((d)[3])              \
        : "r"((a)[0]), "r"((a)[1]), "r"((a)[2]), "r"((a)[3]), "r"(b0_), "r"(b1_))

// ---------------------------------------------------------------------------
// Kernel 1 (fused pre-pass): blocks [0,256) = xtv, blocks [256,4352) = bitpack.
// Independent work fused so the DRAM-bound bitpack overlaps compute-bound xtv.
// ---------------------------------------------------------------------------
__global__ __launch_bounds__(256) void k_pre(const float* __restrict__ x,
                                             const float* __restrict__ W,
                                             const float* __restrict__ a,
                                             const int* __restrict__ adj) {
    __shared__ float sx[16][68];
    __shared__ float sw[16][64];
    __shared__ float sxt[64][68];

    if (blockIdx.x >= 256) {
        // ---------------- bitpack: 16 elements/thread (round-6 best) --------
        size_t tid = (size_t)(blockIdx.x - 256) * 256 + threadIdx.x;
        int lane = threadIdx.x & 31;
        size_t base = tid * 16;
        int row = (int)(base >> 12), col = (int)(base & 4095);
        unsigned bits = 0;
        #pragma unroll
        for (int e = 0; e < 4; e++) {
            int4 v = *(const int4*)(adj + (size_t)row * NN + col + e * 4);
            bits |= ((unsigned)(v.x > 0) << (e * 4)) | ((unsigned)(v.y > 0) << (e * 4 + 1)) |
                    ((unsigned)(v.z > 0) << (e * 4 + 2)) | ((unsigned)(v.w > 0) << (e * 4 + 3));
        }
        unsigned val = bits << (((unsigned)(col >> 4) & 1u) * 16u);
        val |= __shfl_xor_sync(0xffffffffu, val, 1);
        if ((lane & 1) == 0) g_adjT[col >> 5][row] = val;
        return;
    }

    // -------------------- xtv: xt GEMM + scalars + tile build --------------
    const int h = blockIdx.x >> 6, n0 = (blockIdx.x & 63) * 64, t = threadIdx.x;
    const int tx = t & 15, ty = t >> 4;
    const float* Wh = W + h * INF * OF;

    float acc[4][4] = {};
    for (int k0 = 0; k0 < INF; k0 += 16) {
        const int n = t >> 2, kq = (t & 3) * 4;
        float4 xv = *(const float4*)(x + (n0 + n) * INF + k0 + kq);
        const int kk = t & 15, f4 = t >> 4;
        float4 wv = *(const float4*)(Wh + (kk + k0) * OF + f4 * 4);
        __syncthreads();
        sx[kq + 0][n] = xv.x; sx[kq + 1][n] = xv.y;
        sx[kq + 2][n] = xv.z; sx[kq + 3][n] = xv.w;
        *(float4*)&sw[kk][f4 * 4] = wv;
        __syncthreads();
        #pragma unroll
        for (int k = 0; k < 16; k++) {
            float4 av = *(float4*)&sx[k][ty * 4];
            float4 bv = *(float4*)&sw[k][tx * 4];
            acc[0][0] += av.x * bv.x; acc[0][1] += av.x * bv.y; acc[0][2] += av.x * bv.z; acc[0][3] += av.x * bv.w;
            acc[1][0] += av.y * bv.x; acc[1][1] += av.y * bv.y; acc[1][2] += av.y * bv.z; acc[1][3] += av.y * bv.w;
            acc[2][0] += av.z * bv.x; acc[2][1] += av.z * bv.y; acc[2][2] += av.z * bv.z; acc[2][3] += av.z * bv.w;
            acc[3][0] += av.w * bv.x; acc[3][1] += av.w * bv.y; acc[3][2] += av.w * bv.z; acc[3][3] += av.w * bv.w;
        }
    }
    __syncthreads();
    #pragma unroll
    for (int r = 0; r < 4; r++)
        *(float4*)&sxt[ty * 4 + r][tx * 4] = make_float4(acc[r][0], acc[r][1], acc[r][2], acc[r][3]);
    __syncthreads();

    char* tb = g_Vt + (size_t)(h * 64 + (blockIdx.x & 63)) * VCH;

    // per-row src/dst dots; j-data into tile tail
    {
        const int row = t >> 2, qq = t & 3;
        const float* ah = a + h * 2 * OF;
        float s = 0.f, d = 0.f;
        #pragma unroll
        for (int ff = 0; ff < 16; ff++) {
            int f = qq * 16 + ff;
            float v = sxt[row][f];
            s += v * ah[f];
            d += v * ah[OF + f];
        }
        s += __shfl_xor_sync(0xffffffffu, s, 1); s += __shfl_xor_sync(0xffffffffu, s, 2);
        d += __shfl_xor_sync(0xffffffffu, d, 1); d += __shfl_xor_sync(0xffffffffu, d, 2);
        if (qq == 0) {
            g_idat[h][n0 + row] = make_float4(s, expf(s), expf(0.2f * s), 0.f);
            *(float*)(tb + 9216 + row * 4) = d;
            *(float*)(tb + 9472 + row * 4) = expf(d);
            *(float*)(tb + 9728 + row * 4) = expf(0.2f * d);
        }
    }
    __syncthreads();

    // xt tile: fp16; col 64 = 1.0 (Z column); cols 65-71 zero
    for (int idx = t; idx < 64 * 36; idx += 256) {
        int k = idx / 36, u = idx % 36;
        int c0 = u * 2;
        float v0, v1;
        if (c0 < 64)       { v0 = sxt[k][c0]; v1 = sxt[k][c0 + 1]; }
        else if (c0 == 64) { v0 = 1.0f;       v1 = 0.0f; }
        else               { v0 = 0.0f;       v1 = 0.0f; }
        __half2 hp = __floats2half2_rn(v0, v1);
        *(uint32_t*)(tb + k * 144 + u * 4) = *(uint32_t*)&hp;
    }
}

// ---------------------------------------------------------------------------
// Kernel 2 (main): W(fp16) @ [xt | 1]. 16 MMA warps (4 mg x 4 ng) + 1 TMA warp.
// 4-deep xt ring (groups drift), W double-buffered, 1 named barrier/chunk,
// j-data from tile tail (LDS broadcast), adjacency word prefetched.
// ---------------------------------------------------------------------------
#define SM_V   0                      // 4 x 10240 = 40960
#define SM_W   40960                  // 2 x 18432 = 36864
#define SM_Z   77824                  // 128 floats
#define SM_MB  78336                  // vfull[4], vfree[4]
#define SM_TOT 78400

__global__ __launch_bounds__(544, 1) void k_main(float* __restrict__ out) {
    extern __shared__ char smem[];
    const uint32_t sb = smem_u32(smem);
    const int h = blockIdx.y, i0 = blockIdx.x * 128;
    const int t = threadIdx.x, wid = t >> 5, lane = t & 31;
    const uint32_t vfull = sb + SM_MB;        // 4 x 8B
    const uint32_t vfree = sb + SM_MB + 32;   // 4 x 8B

    if (t == 0) {
        #pragma unroll
        for (int s = 0; s < 4; s++) {
            MBAR_INIT(vfull + s * 8, 1);
            MBAR_INIT(vfree + s * 8, 16);
        }
    }
    __syncthreads();

    const int mg = wid >> 2;
    const int ng = (wid + (wid >> 2)) & 3;   // diagonal remap of ng over SMSPs
    const int q  = wid & 3;                  // j-quarter for stage A

    float d[4][4] = {}, dz[2][4] = {};

    if (wid == 16) {
        // ----------------------------- TMA warp -----------------------------
        if (lane == 0) {
            #pragma unroll 1
            for (int m = 0; m < 64; m++) {
                const int b = m & 3;
                if (m >= 4) MBAR_WAIT(vfree + b * 8, ((m - 4) >> 2) & 1);
                asm volatile("mbarrier.arrive.expect_tx.shared.b64 _, [%0], %1;"
                             :: "r"(vfull + b * 8), "r"((uint32_t)VCH) : "memory");
                const char* src = g_Vt + (size_t)(h * 64 + m) * VCH;
                uint64_t sg; asm("cvta.to.global.u64 %0, %1;" : "=l"(sg) : "l"(src));
                asm volatile("cp.async.bulk.shared::cluster.global.mbarrier::complete_tx::bytes "
                             "[%0], [%1], %2, [%3];"
                             :: "r"(sb + SM_V + b * VCH), "l"(sg), "r"((uint32_t)VCH),
                                "r"(vfull + b * 8) : "memory");
            }
        }
    } else {
        // --------------------------- 16 MMA warps ---------------------------
        const int barid = 1 + mg;
        const int rowA = mg * 32 + lane;
        const float4 id = g_idat[h][i0 + rowA];
        const float th = -id.x, A1 = id.y, A2 = id.z;   // branch 1: dst >= -src

        const uint32_t aOff = (uint32_t)((mg * 32 + (lane & 15)) * 144 + (lane >> 4) * 16);
        const uint32_t bO = (uint32_t)((lane & 15) * 144 + (lane >> 4) * 16 + ng * 32);
        const uint32_t bZ = (uint32_t)((lane & 15) * 144 + 128);

        // stage A: 16-j strip of fp16 W from tile-tail j-data (broadcast LDS)
        auto stageA = [&](int mc, int wsel, unsigned w) {
            const char* jb = smem + SM_V + (mc & 3) * VCH + 9216 + q * 64;
            uint32_t vv[8];
            #pragma unroll
            for (int u = 0; u < 4; u++) {
                float4 f0 = *(const float4*)(jb + u * 16);          // dst
                float4 f1 = *(const float4*)(jb + 256 + u * 16);    // e1
                float4 f2 = *(const float4*)(jb + 512 + u * 16);    // e2
                float w0 = (f0.x >= th) ? A1 * f1.x : A2 * f2.x;
                float w1 = (f0.y >= th) ? A1 * f1.y : A2 * f2.y;
                w0 = ((w >> (4 * u + 0)) & 1u) ? w0 : 0.f;
                w1 = ((w >> (4 * u + 1)) & 1u) ? w1 : 0.f;
                __half2 p0 = __floats2half2_rn(w0, w1);
                w0 = (f0.z >= th) ? A1 * f1.z : A2 * f2.z;
                w1 = (f0.w >= th) ? A1 * f1.w : A2 * f2.w;
                w0 = ((w >> (4 * u + 2)) & 1u) ? w0 : 0.f;
                w1 = ((w >> (4 * u + 3)) & 1u) ? w1 : 0.f;
                __half2 p1 = __floats2half2_rn(w0, w1);
                vv[2 * u]     = *(uint32_t*)&p0;
                vv[2 * u + 1] = *(uint32_t*)&p1;
            }
            char* pr = smem + SM_W + wsel * 18432 + rowA * 144 + q * 32;
            *(uint4*)(pr)      = make_uint4(vv[0], vv[1], vv[2], vv[3]);
            *(uint4*)(pr + 16) = make_uint4(vv[4], vv[5], vv[6], vv[7]);
        };

        // prologue: chunk 0
        unsigned wCur = g_adjT[q >> 1][i0 + rowA] >> ((q & 1) * 16);
        MBAR_WAIT(vfull + 0, 0);
        stageA(0, 0, wCur);
        BAR_SYNC(barid, 128);

        int wsel = 0;
        #pragma unroll 1
        for (int m = 0; m < 64; m++) {
            const int slot = m & 3;
            // prefetch next adjacency word (hides LDG under MMA)
            unsigned wNext = 0;
            if (m < 63)
                wNext = g_adjT[(m + 1) * 2 + (q >> 1)][i0 + rowA] >> ((q & 1) * 16);

            const uint32_t vb = sb + SM_V + slot * VCH;
            const uint32_t aW = sb + SM_W + wsel * 18432 + aOff;
            #pragma unroll
            for (int ks = 0; ks < 4; ks++) {
                uint32_t af[2][4];
                LDSM_X4(af[0], aW + ks * 32);
                LDSM_X4(af[1], aW + 2304 + ks * 32);
                const uint32_t kb = vb + (uint32_t)ks * 2304;
                uint32_t bf[4];
                LDSM_X4T(bf, kb + bO);               // xt (fp16)
                MMA(d[0], af[0], bf[0], bf[1]); MMA(d[1], af[0], bf[2], bf[3]);
                MMA(d[2], af[1], bf[0], bf[1]); MMA(d[3], af[1], bf[2], bf[3]);
                if (ng == 3) {                       // Z: ones column
                    uint32_t c2[2];
                    LDSM_X2T(c2, kb + bZ);
                    MMA(dz[0], af[0], c2[0], c2[1]);
                    MMA(dz[1], af[1], c2[0], c2[1]);
                }
            }
            if (lane == 0) MBAR_ARRIVE(vfree + slot * 8);
            if (m < 63) {
                // stageA(m+1) needs slot m+1 tile (j-data in its tail)
                MBAR_WAIT(vfull + ((m + 1) & 3) * 8, ((m + 1) >> 2) & 1);
                stageA(m + 1, wsel ^ 1, wNext);
                wsel ^= 1;
                BAR_SYNC(barid, 128);
            }
        }
    }

    __syncthreads();
    float* zs = (float*)(smem + SM_Z);
    if (wid < 16 && ng == 3 && (lane & 3) == 0) {
        #pragma unroll
        for (int mt = 0; mt < 2; mt++) {
            int row = mg * 32 + mt * 16 + (lane >> 2);
            zs[row]     = dz[mt][0];
            zs[row + 8] = dz[mt][2];
        }
    }
    __syncthreads();
    if (wid < 16) {
        #pragma unroll
        for (int mt = 0; mt < 2; mt++) {
            int rlo = mg * 32 + mt * 16 + (lane >> 2);
            int rhi = rlo + 8;
            float zlo = 1.0f / zs[rlo];
            float zhi = 1.0f / zs[rhi];
            #pragma unroll
            for (int n8 = 0; n8 < 2; n8++) {
                int col = h * OF + ng * 16 + n8 * 8 + (lane & 3) * 2;
                float* dd = d[mt * 2 + n8];
                float2 plo = make_float2(dd[0] * zlo, dd[1] * zlo);
                float2 phi = make_float2(dd[2] * zhi, dd[3] * zhi);
                *(float2*)(out + (size_t)(i0 + rlo) * (NH * OF) + col) = plo;
                *(float2*)(out + (size_t)(i0 + rhi) * (NH * OF) + col) = phi;
            }
        }
    }
}

// ---------------------------------------------------------------------------
extern "C" void kernel_launch(void* const* d_in, const int* in_sizes, int n_in,
                              void* d_out, int out_size) {
    const float* x   = (const float*)d_in[0];  // [4096, 256]
    const float* W   = (const float*)d_in[1];  // [4, 256, 64]
    const float* a   = (const float*)d_in[2];  // [4, 128]
    const int*   adj = (const int*)d_in[3];    // [4096, 4096]
    float* out = (float*)d_out;                // [4096, 256]
    (void)in_sizes; (void)n_in; (void)out_size;

    cudaFuncSetAttribute(k_main, cudaFuncAttributeMaxDynamicSharedMemorySize, SM_TOT);

    k_pre<<<256 + (NN * NN / 16) / 256, 256>>>(x, W, a, adj);
    k_main<<<dim3(NN / 128, NH), 544, SM_TOT>>>(out);
}

// round 10
// speedup vs baseline: 3.3394x; 1.0435x over previous
#include <cuda_runtime.h>
#include <cuda_fp16.h>
#include <cstdint>

#define NN 4096
#define INF 256
#define OF 64
#define NH 4

// ---------------------------------------------------------------------------
// Scratch globals
// ---------------------------------------------------------------------------
__device__ float4   g_idat[NH][NN];        // {src, exp(src), exp(0.2*src), 0}
__device__ unsigned g_adjT[NN / 32][NN];   // adjacency bits [wordcol][row]
// xt tiles: per (h,chunk): fp16 seg [64 k][72 n] (rows 144B) + 1KB tail:
//   [9216,9472) dst f32[64]   [9472,9728) e1 f32[64]   [9728,9984) e2 f32[64]
#define SEGB 9216
#define VCH  10240
__device__ __align__(16) char g_Vt[NH * 64 * VCH];

// ---------------------------------------------------------------------------
// PTX helpers (family-generic: no tcgen05 on compute_103 virtual target)
// ---------------------------------------------------------------------------
__device__ __forceinline__ uint32_t smem_u32(const void* p) {
    uint32_t a;
    asm("{ .reg .u64 t; cvta.to.shared.u64 t, %1; cvt.u32.u64 %0, t; }" : "=r"(a) : "l"(p));
    return a;
}
#define MBAR_INIT(a, n) asm volatile("mbarrier.init.shared.b64 [%0], %1;" :: "r"(a), "r"(n) : "memory")
#define MBAR_WAIT(a, ph) do {                                                            \
    uint32_t _m = (a), _p = (ph), _d;                                                    \
    asm volatile("{ .reg .pred p; mbarrier.try_wait.parity.acquire.cta.shared::cta.b64 " \
                 "p, [%1], %2; selp.b32 %0, 1, 0, p; }" : "=r"(_d) : "r"(_m), "r"(_p) : "memory"); \
    if (!_d) {                                                                           \
        asm volatile("{ .reg .pred P1; WL_%=: mbarrier.try_wait.parity.acquire.cta.shared::cta.b64 " \
                     "P1, [%0], %1, 0x989680; @P1 bra.uni WD_%=; bra.uni WL_%=; WD_%=: }" \
                     :: "r"(_m), "r"(_p) : "memory");                                    \
    }                                                                                    \
} while (0)
#define MBAR_ARRIVE(a) asm volatile("mbarrier.arrive.shared.b64 _, [%0];" :: "r"(a) : "memory")
#define BAR_SYNC(id, n) asm volatile("bar.sync %0, %1;" :: "r"(id), "r"(n) : "memory")

#define LDSM_X4(r, a)                                                         \
    asm volatile("ldmatrix.sync.aligned.m8n8.x4.shared.b16 {%0,%1,%2,%3}, [%4];" \
        : "=r"((r)[0]), "=r"((r)[1]), "=r"((r)[2]), "=r"((r)[3]) : "r"(a))
#define LDSM_X4T(r, a)                                                        \
    asm volatile("ldmatrix.sync.aligned.m8n8.x4.trans.shared.b16 {%0,%1,%2,%3}, [%4];" \
        : "=r"((r)[0]), "=r"((r)[1]), "=r"((r)[2]), "=r"((r)[3]) : "r"(a))
#define LDSM_X2T(r, a)                                                        \
    asm volatile("ldmatrix.sync.aligned.m8n8.x2.trans.shared.b16 {%0,%1}, [%2];" \
        : "=r"((r)[0]), "=r"((r)[1]) : "r"(a))

#define MMA(d, a, b0_, b1_)                                                   \
    asm volatile("mma.sync.aligned.m16n8k16.row.col.f32.f16.f16.f32 "         \
        "{%0,%1,%2,%3},{%4,%5,%6,%7},{%8,%9},{%0,%1,%2,%3};"                  \
        : "+f"((d)[0]), "+f"((d)[1]), "+f"((d)[2]), "+f"((d)[3])              \
        : "r"((a)[0]), "r"((a)[1]), "r"((a)[2]), "r"((a)[3]), "r"(b0_), "r"(b1_))

// ---------------------------------------------------------------------------
// Kernel 1: adjacency bitpack (transposed), 16 elements/thread (measured best)
// ---------------------------------------------------------------------------
__global__ __launch_bounds__(256) void k_bitpack(const int* __restrict__ adj) {
    size_t tid = (size_t)blockIdx.x * 256 + threadIdx.x;
    int lane = threadIdx.x & 31;
    size_t base = tid * 16;
    int row = (int)(base >> 12), col = (int)(base & 4095);
    unsigned bits = 0;
    #pragma unroll
    for (int e = 0; e < 4; e++) {
        int4 v = *(const int4*)(adj + (size_t)row * NN + col + e * 4);
        bits |= ((unsigned)(v.x > 0) << (e * 4)) | ((unsigned)(v.y > 0) << (e * 4 + 1)) |
                ((unsigned)(v.z > 0) << (e * 4 + 2)) | ((unsigned)(v.w > 0) << (e * 4 + 3));
    }
    unsigned val = bits << (((unsigned)(col >> 4) & 1u) * 16u);
    val |= __shfl_xor_sync(0xffffffffu, val, 1);
    if ((lane & 1) == 0) g_adjT[col >> 5][row] = val;
}

// ---------------------------------------------------------------------------
// Kernel 2: xt GEMM + per-row scalars + fp16 xt-tile build (j-data in tail).
// ---------------------------------------------------------------------------
__global__ __launch_bounds__(256) void k_xtv(const float* __restrict__ x,
                                             const float* __restrict__ W,
                                             const float* __restrict__ a) {
    __shared__ float sx[16][68];
    __shared__ float sw[16][64];
    __shared__ float sxt[64][68];
    const int h = blockIdx.y, n0 = blockIdx.x * 64, t = threadIdx.x;
    const int tx = t & 15, ty = t >> 4;
    const float* Wh = W + h * INF * OF;

    float acc[4][4] = {};
    for (int k0 = 0; k0 < INF; k0 += 16) {
        const int n = t >> 2, kq = (t & 3) * 4;
        float4 xv = *(const float4*)(x + (n0 + n) * INF + k0 + kq);
        const int kk = t & 15, f4 = t >> 4;
        float4 wv = *(const float4*)(Wh + (kk + k0) * OF + f4 * 4);
        __syncthreads();
        sx[kq + 0][n] = xv.x; sx[kq + 1][n] = xv.y;
        sx[kq + 2][n] = xv.z; sx[kq + 3][n] = xv.w;
        *(float4*)&sw[kk][f4 * 4] = wv;
        __syncthreads();
        #pragma unroll
        for (int k = 0; k < 16; k++) {
            float4 av = *(float4*)&sx[k][ty * 4];
            float4 bv = *(float4*)&sw[k][tx * 4];
            acc[0][0] += av.x * bv.x; acc[0][1] += av.x * bv.y; acc[0][2] += av.x * bv.z; acc[0][3] += av.x * bv.w;
            acc[1][0] += av.y * bv.x; acc[1][1] += av.y * bv.y; acc[1][2] += av.y * bv.z; acc[1][3] += av.y * bv.w;
            acc[2][0] += av.z * bv.x; acc[2][1] += av.z * bv.y; acc[2][2] += av.z * bv.z; acc[2][3] += av.z * bv.w;
            acc[3][0] += av.w * bv.x; acc[3][1] += av.w * bv.y; acc[3][2] += av.w * bv.z; acc[3][3] += av.w * bv.w;
        }
    }
    __syncthreads();
    #pragma unroll
    for (int r = 0; r < 4; r++)
        *(float4*)&sxt[ty * 4 + r][tx * 4] = make_float4(acc[r][0], acc[r][1], acc[r][2], acc[r][3]);
    __syncthreads();

    char* tb = g_Vt + (size_t)(h * 64 + blockIdx.x) * VCH;

    {
        const int row = t >> 2, qq = t & 3;
        const float* ah = a + h * 2 * OF;
        float s = 0.f, d = 0.f;
        #pragma unroll
        for (int ff = 0; ff < 16; ff++) {
            int f = qq * 16 + ff;
            float v = sxt[row][f];
            s += v * ah[f];
            d += v * ah[OF + f];
        }
        s += __shfl_xor_sync(0xffffffffu, s, 1); s += __shfl_xor_sync(0xffffffffu, s, 2);
        d += __shfl_xor_sync(0xffffffffu, d, 1); d += __shfl_xor_sync(0xffffffffu, d, 2);
        if (qq == 0) {
            g_idat[h][n0 + row] = make_float4(s, expf(s), expf(0.2f * s), 0.f);
            *(float*)(tb + 9216 + row * 4) = d;
            *(float*)(tb + 9472 + row * 4) = expf(d);
            *(float*)(tb + 9728 + row * 4) = expf(0.2f * d);
        }
    }
    __syncthreads();

    for (int idx = t; idx < 64 * 36; idx += 256) {
        int k = idx / 36, u = idx % 36;
        int c0 = u * 2;
        float v0, v1;
        if (c0 < 64)       { v0 = sxt[k][c0]; v1 = sxt[k][c0 + 1]; }
        else if (c0 == 64) { v0 = 1.0f;       v1 = 0.0f; }
        else               { v0 = 0.0f;       v1 = 0.0f; }
        __half2 hp = __floats2half2_rn(v0, v1);
        *(uint32_t*)(tb + k * 144 + u * 4) = *(uint32_t*)&hp;
    }
}

// ---------------------------------------------------------------------------
// Kernel 3 (main): M=64 CTA, 288 threads (8 MMA warps + 1 TMA), 2 CTAs/SM.
// 3-deep xt ring, W double-buffered, 1 named barrier per chunk per group.
// ---------------------------------------------------------------------------
#define SM_V   0                      // 3 x 10240 = 30720
#define SM_W   30720                  // 2 x 9216 = 18432
#define SM_Z   49152                  // 64 floats
#define SM_MB  49408                  // vfull[3], vfree[3]
#define SM_TOT 49472

__global__ __launch_bounds__(288, 2) void k_main(float* __restrict__ out) {
    extern __shared__ char smem[];
    const uint32_t sb = smem_u32(smem);
    const int h = blockIdx.y, i0 = blockIdx.x * 64;
    const int t = threadIdx.x, wid = t >> 5, lane = t & 31;
    const uint32_t vfull = sb + SM_MB;        // 3 x 8B
    const uint32_t vfree = sb + SM_MB + 24;   // 3 x 8B

    if (t == 0) {
        #pragma unroll
        for (int s = 0; s < 3; s++) {
            MBAR_INIT(vfull + s * 8, 1);
            MBAR_INIT(vfree + s * 8, 8);
        }
    }
    __syncthreads();

    const int mg = wid >> 2;                 // 0..1
    const int ng = (wid + mg) & 3;           // diagonal remap over SMSPs
    const int q  = wid & 3;                  // j-quarter for stage A

    float d[4][4] = {}, dz[2][4] = {};

    if (wid == 8) {
        // ----------------------------- TMA warp -----------------------------
        if (lane == 0) {
            int slot = 0, mph = 0;
            #pragma unroll 1
            for (int m = 0; m < 64; m++) {
                if (m >= 3) MBAR_WAIT(vfree + slot * 8, mph ^ 1);
                asm volatile("mbarrier.arrive.expect_tx.shared.b64 _, [%0], %1;"
                             :: "r"(vfull + slot * 8), "r"((uint32_t)VCH) : "memory");
                const char* src = g_Vt + (size_t)(h * 64 + m) * VCH;
                uint64_t sg; asm("cvta.to.global.u64 %0, %1;" : "=l"(sg) : "l"(src));
                asm volatile("cp.async.bulk.shared::cluster.global.mbarrier::complete_tx::bytes "
                             "[%0], [%1], %2, [%3];"
                             :: "r"(sb + SM_V + slot * VCH), "l"(sg), "r"((uint32_t)VCH),
                                "r"(vfull + slot * 8) : "memory");
                if (++slot == 3) { slot = 0; mph ^= 1; }
            }
        }
    } else {
        // ---------------------------- 8 MMA warps ---------------------------
        const int barid = 1 + mg;
        const int rowA = mg * 32 + lane;     // 0..63
        const float4 id = g_idat[h][i0 + rowA];
        const float th = -id.x, A1 = id.y, A2 = id.z;   // branch 1: dst >= -src

        const uint32_t aOff = (uint32_t)((mg * 32 + (lane & 15)) * 144 + (lane >> 4) * 16);
        const uint32_t bO = (uint32_t)((lane & 15) * 144 + (lane >> 4) * 16 + ng * 32);
        const uint32_t bZ = (uint32_t)((lane & 15) * 144 + 128);

        // stage A: 16-j strip of fp16 W from tile-tail j-data (broadcast LDS)
        auto stageA = [&](int slotIdx, int wsel, unsigned w) {
            const char* jb = smem + SM_V + slotIdx * VCH + 9216 + q * 64;
            uint32_t vv[8];
            #pragma unroll
            for (int u = 0; u < 4; u++) {
                float4 f0 = *(const float4*)(jb + u * 16);          // dst
                float4 f1 = *(const float4*)(jb + 256 + u * 16);    // e1
                float4 f2 = *(const float4*)(jb + 512 + u * 16);    // e2
                float w0 = (f0.x >= th) ? A1 * f1.x : A2 * f2.x;
                float w1 = (f0.y >= th) ? A1 * f1.y : A2 * f2.y;
                w0 = ((w >> (4 * u + 0)) & 1u) ? w0 : 0.f;
                w1 = ((w >> (4 * u + 1)) & 1u) ? w1 : 0.f;
                __half2 p0 = __floats2half2_rn(w0, w1);
                w0 = (f0.z >= th) ? A1 * f1.z : A2 * f2.z;
                w1 = (f0.w >= th) ? A1 * f1.w : A2 * f2.w;
                w0 = ((w >> (4 * u + 2)) & 1u) ? w0 : 0.f;
                w1 = ((w >> (4 * u + 3)) & 1u) ? w1 : 0.f;
                __half2 p1 = __floats2half2_rn(w0, w1);
                vv[2 * u]     = *(uint32_t*)&p0;
                vv[2 * u + 1] = *(uint32_t*)&p1;
            }
            char* pr = smem + SM_W + wsel * 9216 + rowA * 144 + q * 32;
            *(uint4*)(pr)      = make_uint4(vv[0], vv[1], vv[2], vv[3]);
            *(uint4*)(pr + 16) = make_uint4(vv[4], vv[5], vv[6], vv[7]);
        };

        // prologue: chunk 0
        unsigned wCur = g_adjT[q >> 1][i0 + rowA] >> ((q & 1) * 16);
        MBAR_WAIT(vfull + 0, 0);
        stageA(0, 0, wCur);
        BAR_SYNC(barid, 128);

        int wsel = 0, slot = 0, cph = 0;
        #pragma unroll 1
        for (int m = 0; m < 64; m++) {
            // prefetch next adjacency word (hides LDG under MMA)
            unsigned wNext = 0;
            if (m < 63)
                wNext = g_adjT[(m + 1) * 2 + (q >> 1)][i0 + rowA] >> ((q & 1) * 16);

            const uint32_t vb = sb + SM_V + slot * VCH;
            const uint32_t aW = sb + SM_W + wsel * 9216 + aOff;
            #pragma unroll
            for (int ks = 0; ks < 4; ks++) {
                uint32_t af[2][4];
                LDSM_X4(af[0], aW + ks * 32);
                LDSM_X4(af[1], aW + 2304 + ks * 32);
                const uint32_t kb = vb + (uint32_t)ks * 2304;
                uint32_t bf[4];
                LDSM_X4T(bf, kb + bO);               // xt (fp16)
                MMA(d[0], af[0], bf[0], bf[1]); MMA(d[1], af[0], bf[2], bf[3]);
                MMA(d[2], af[1], bf[0], bf[1]); MMA(d[3], af[1], bf[2], bf[3]);
                if (ng == 3) {                       // Z: ones column
                    uint32_t c2[2];
                    LDSM_X2T(c2, kb + bZ);
                    MMA(dz[0], af[0], c2[0], c2[1]);
                    MMA(dz[1], af[1], c2[0], c2[1]);
                }
            }
            if (lane == 0) MBAR_ARRIVE(vfree + slot * 8);
            if (m < 63) {
                if (++slot == 3) { slot = 0; cph ^= 1; }
                MBAR_WAIT(vfull + slot * 8, cph);    // tile m+1 present
                stageA(slot, wsel ^ 1, wNext);
                wsel ^= 1;
                BAR_SYNC(barid, 128);                // W ready for next chunk
            }
        }
    }

    __syncthreads();
    float* zs = (float*)(smem + SM_Z);
    if (wid < 8 && ng == 3 && (lane & 3) == 0) {
        #pragma unroll
        for (int mt = 0; mt < 2; mt++) {
            int row = mg * 32 + mt * 16 + (lane >> 2);
            zs[row]     = dz[mt][0];
            zs[row + 8] = dz[mt][2];
        }
    }
    __syncthreads();
    if (wid < 8) {
        #pragma unroll
        for (int mt = 0; mt < 2; mt++) {
            int rlo = mg * 32 + mt * 16 + (lane >> 2);
            int rhi = rlo + 8;
            float zlo = 1.0f / zs[rlo];
            float zhi = 1.0f / zs[rhi];
            #pragma unroll
            for (int n8 = 0; n8 < 2; n8++) {
                int col = h * OF + ng * 16 + n8 * 8 + (lane & 3) * 2;
                float* dd = d[mt * 2 + n8];
                float2 plo = make_float2(dd[0] * zlo, dd[1] * zlo);
                float2 phi = make_float2(dd[2] * zhi, dd[3] * zhi);
                *(float2*)(out + (size_t)(i0 + rlo) * (NH * OF) + col) = plo;
                *(float2*)(out + (size_t)(i0 + rhi) * (NH * OF) + col) = phi;
            }
        }
    }
}

// ---------------------------------------------------------------------------
extern "C" void kernel_launch(void* const* d_in, const int* in_sizes, int n_in,
                              void* d_out, int out_size) {
    const float* x   = (const float*)d_in[0];  // [4096, 256]
    const float* W   = (const float*)d_in[1];  // [4, 256, 64]
    const float* a   = (const float*)d_in[2];  // [4, 128]
    const int*   adj = (const int*)d_in[3];    // [4096, 4096]
    float* out = (float*)d_out;                // [4096, 256]
    (void)in_sizes; (void)n_in; (void)out_size;

    cudaFuncSetAttribute(k_main, cudaFuncAttributeMaxDynamicSharedMemorySize, SM_TOT);

    k_bitpack<<<(NN * NN / 16) / 256, 256>>>(adj);
    k_xtv<<<dim3(NN / 64, NH), 256>>>(x, W, a);
    k_main<<<dim3(NN / 64, NH), 288, SM_TOT>>>(out);
}

// round 11
// speedup vs baseline: 3.7156x; 1.1127x over previous
#include <cuda_runtime.h>
#include <cuda_fp16.h>
#include <cstdint>

#define NN 4096
#define INF 256
#define OF 64
#define NH 4

// ---------------------------------------------------------------------------
// Scratch globals
// ---------------------------------------------------------------------------
__device__ float4   g_idat[NH][NN];        // {src, exp(src), exp(0.2*src), 0}
__device__ unsigned g_adjT[NN / 32][NN];   // adjacency bits [wordcol][row]
// xt tiles: per (h,chunk): fp16 seg [64 k][64 n] (rows 144B) + 1KB tail:
//   [9216,9472) dst f32[64]   [9472,9728) e1 f32[64]   [9728,9984) e2 f32[64]
#define SEGB 9216
#define VCH  10240
__device__ __align__(16) char g_Vt[NH * 64 * VCH];

// ---------------------------------------------------------------------------
// PTX helpers (family-generic: no tcgen05 on compute_103 virtual target)
// ---------------------------------------------------------------------------
__device__ __forceinline__ uint32_t smem_u32(const void* p) {
    uint32_t a;
    asm("{ .reg .u64 t; cvta.to.shared.u64 t, %1; cvt.u32.u64 %0, t; }" : "=r"(a) : "l"(p));
    return a;
}
#define MBAR_INIT(a, n) asm volatile("mbarrier.init.shared.b64 [%0], %1;" :: "r"(a), "r"(n) : "memory")
#define MBAR_WAIT(a, ph) do {                                                            \
    uint32_t _m = (a), _p = (ph), _d;                                                    \
    asm volatile("{ .reg .pred p; mbarrier.try_wait.parity.acquire.cta.shared::cta.b64 " \
                 "p, [%1], %2; selp.b32 %0, 1, 0, p; }" : "=r"(_d) : "r"(_m), "r"(_p) : "memory"); \
    if (!_d) {                                                                           \
        asm volatile("{ .reg .pred P1; WL_%=: mbarrier.try_wait.parity.acquire.cta.shared::cta.b64 " \
                     "P1, [%0], %1, 0x989680; @P1 bra.uni WD_%=; bra.uni WL_%=; WD_%=: }" \
                     :: "r"(_m), "r"(_p) : "memory");                                    \
    }                                                                                    \
} while (0)
#define MBAR_ARRIVE(a) asm volatile("mbarrier.arrive.shared.b64 _, [%0];" :: "r"(a) : "memory")
#define BAR_SYNC(id, n) asm volatile("bar.sync %0, %1;" :: "r"(id), "r"(n) : "memory")

#define LDSM_X4(r, a)                                                         \
    asm volatile("ldmatrix.sync.aligned.m8n8.x4.shared.b16 {%0,%1,%2,%3}, [%4];" \
        : "=r"((r)[0]), "=r"((r)[1]), "=r"((r)[2]), "=r"((r)[3]) : "r"(a))
#define LDSM_X4T(r, a)                                                        \
    asm volatile("ldmatrix.sync.aligned.m8n8.x4.trans.shared.b16 {%0,%1,%2,%3}, [%4];" \
        : "=r"((r)[0]), "=r"((r)[1]), "=r"((r)[2]), "=r"((r)[3]) : "r"(a))

#define MMA(d, a, b0_, b1_)                                                   \
    asm volatile("mma.sync.aligned.m16n8k16.row.col.f32.f16.f16.f32 "         \
        "{%0,%1,%2,%3},{%4,%5,%6,%7},{%8,%9},{%0,%1,%2,%3};"                  \
        : "+f"((d)[0]), "+f"((d)[1]), "+f"((d)[2]), "+f"((d)[3])              \
        : "r"((a)[0]), "r"((a)[1]), "r"((a)[2]), "r"((a)[3]), "r"(b0_), "r"(b1_))

// ---------------------------------------------------------------------------
// Kernel 1: adjacency bitpack (transposed), 16 elements/thread (measured best)
// ---------------------------------------------------------------------------
__global__ __launch_bounds__(256) void k_bitpack(const int* __restrict__ adj) {
    size_t tid = (size_t)blockIdx.x * 256 + threadIdx.x;
    int lane = threadIdx.x & 31;
    size_t base = tid * 16;
    int row = (int)(base >> 12), col = (int)(base & 4095);
    unsigned bits = 0;
    #pragma unroll
    for (int e = 0; e < 4; e++) {
        int4 v = *(const int4*)(adj + (size_t)row * NN + col + e * 4);
        bits |= ((unsigned)(v.x > 0) << (e * 4)) | ((unsigned)(v.y > 0) << (e * 4 + 1)) |
                ((unsigned)(v.z > 0) << (e * 4 + 2)) | ((unsigned)(v.w > 0) << (e * 4 + 3));
    }
    unsigned val = bits << (((unsigned)(col >> 4) & 1u) * 16u);
    val |= __shfl_xor_sync(0xffffffffu, val, 1);
    if ((lane & 1) == 0) g_adjT[col >> 5][row] = val;
}

// ---------------------------------------------------------------------------
// Kernel 2: xt GEMM + per-row scalars + fp16 xt-tile build (j-data in tail).
// ---------------------------------------------------------------------------
__global__ __launch_bounds__(256) void k_xtv(const float* __restrict__ x,
                                             const float* __restrict__ W,
                                             const float* __restrict__ a) {
    __shared__ float sx[16][68];
    __shared__ float sw[16][64];
    __shared__ float sxt[64][68];
    const int h = blockIdx.y, n0 = blockIdx.x * 64, t = threadIdx.x;
    const int tx = t & 15, ty = t >> 4;
    const float* Wh = W + h * INF * OF;

    float acc[4][4] = {};
    for (int k0 = 0; k0 < INF; k0 += 16) {
        const int n = t >> 2, kq = (t & 3) * 4;
        float4 xv = *(const float4*)(x + (n0 + n) * INF + k0 + kq);
        const int kk = t & 15, f4 = t >> 4;
        float4 wv = *(const float4*)(Wh + (kk + k0) * OF + f4 * 4);
        __syncthreads();
        sx[kq + 0][n] = xv.x; sx[kq + 1][n] = xv.y;
        sx[kq + 2][n] = xv.z; sx[kq + 3][n] = xv.w;
        *(float4*)&sw[kk][f4 * 4] = wv;
        __syncthreads();
        #pragma unroll
        for (int k = 0; k < 16; k++) {
            float4 av = *(float4*)&sx[k][ty * 4];
            float4 bv = *(float4*)&sw[k][tx * 4];
            acc[0][0] += av.x * bv.x; acc[0][1] += av.x * bv.y; acc[0][2] += av.x * bv.z; acc[0][3] += av.x * bv.w;
            acc[1][0] += av.y * bv.x; acc[1][1] += av.y * bv.y; acc[1][2] += av.y * bv.z; acc[1][3] += av.y * bv.w;
            acc[2][0] += av.z * bv.x; acc[2][1] += av.z * bv.y; acc[2][2] += av.z * bv.z; acc[2][3] += av.z * bv.w;
            acc[3][0] += av.w * bv.x; acc[3][1] += av.w * bv.y; acc[3][2] += av.w * bv.z; acc[3][3] += av.w * bv.w;
        }
    }
    __syncthreads();
    #pragma unroll
    for (int r = 0; r < 4; r++)
        *(float4*)&sxt[ty * 4 + r][tx * 4] = make_float4(acc[r][0], acc[r][1], acc[r][2], acc[r][3]);
    __syncthreads();

    char* tb = g_Vt + (size_t)(h * 64 + blockIdx.x) * VCH;

    {
        const int row = t >> 2, qq = t & 3;
        const float* ah = a + h * 2 * OF;
        float s = 0.f, d = 0.f;
        #pragma unroll
        for (int ff = 0; ff < 16; ff++) {
            int f = qq * 16 + ff;
            float v = sxt[row][f];
            s += v * ah[f];
            d += v * ah[OF + f];
        }
        s += __shfl_xor_sync(0xffffffffu, s, 1); s += __shfl_xor_sync(0xffffffffu, s, 2);
        d += __shfl_xor_sync(0xffffffffu, d, 1); d += __shfl_xor_sync(0xffffffffu, d, 2);
        if (qq == 0) {
            g_idat[h][n0 + row] = make_float4(s, expf(s), expf(0.2f * s), 0.f);
            *(float*)(tb + 9216 + row * 4) = d;
            *(float*)(tb + 9472 + row * 4) = expf(d);
            *(float*)(tb + 9728 + row * 4) = expf(0.2f * d);
        }
    }
    __syncthreads();

    for (int idx = t; idx < 64 * 32; idx += 256) {
        int k = idx >> 5, u = idx & 31;
        int c0 = u * 2;
        __half2 hp = __floats2half2_rn(sxt[k][c0], sxt[k][c0 + 1]);
        *(uint32_t*)(tb + k * 144 + u * 4) = *(uint32_t*)&hp;
    }
}

// ---------------------------------------------------------------------------
// Kernel 3 (main): M=64 CTA, 160 threads (4 MMA warps mg2 x ng2 + 1 TMA warp),
// 2 CTAs/SM. Z accumulated in stage A (fp32 regs + shared atomics) — no Z MMA.
// 3-deep xt ring, W double-buffered, 1 named barrier per chunk.
// ---------------------------------------------------------------------------
#define SM_V   0                      // 3 x 10240 = 30720
#define SM_W   30720                  // 2 x 9216 = 18432
#define SM_Z   49152                  // 64 floats
#define SM_MB  49408                  // vfull[3], vfree[3]
#define SM_TOT 49472

__global__ __launch_bounds__(160, 2) void k_main(float* __restrict__ out) {
    extern __shared__ char smem[];
    const uint32_t sb = smem_u32(smem);
    const int h = blockIdx.y, i0 = blockIdx.x * 64;
    const int t = threadIdx.x, wid = t >> 5, lane = t & 31;
    const uint32_t vfull = sb + SM_MB;        // 3 x 8B
    const uint32_t vfree = sb + SM_MB + 24;   // 3 x 8B
    float* zs = (float*)(smem + SM_Z);

    if (t == 0) {
        #pragma unroll
        for (int s = 0; s < 3; s++) {
            MBAR_INIT(vfull + s * 8, 1);
            MBAR_INIT(vfree + s * 8, 4);
        }
    }
    if (t < 64) zs[t] = 0.f;
    __syncthreads();

    if (wid == 4) {
        // ----------------------------- TMA warp -----------------------------
        if (lane == 0) {
            int slot = 0, mph = 0;
            #pragma unroll 1
            for (int m = 0; m < 64; m++) {
                if (m >= 3) MBAR_WAIT(vfree + slot * 8, mph ^ 1);
                asm volatile("mbarrier.arrive.expect_tx.shared.b64 _, [%0], %1;"
                             :: "r"(vfull + slot * 8), "r"((uint32_t)VCH) : "memory");
                const char* src = g_Vt + (size_t)(h * 64 + m) * VCH;
                uint64_t sg; asm("cvta.to.global.u64 %0, %1;" : "=l"(sg) : "l"(src));
                asm volatile("cp.async.bulk.shared::cluster.global.mbarrier::complete_tx::bytes "
                             "[%0], [%1], %2, [%3];"
                             :: "r"(sb + SM_V + slot * VCH), "l"(sg), "r"((uint32_t)VCH),
                                "r"(vfull + slot * 8) : "memory");
                if (++slot == 3) { slot = 0; mph ^= 1; }
            }
        }
    } else {
        // ---------------------------- 4 MMA warps ---------------------------
        const int q = wid;                    // j-quarter for stage A (0..3)
        const int mgw = wid >> 1;             // row half for stage B
        const int ngw = wid & 1;              // col half for stage B
        const int r0 = lane, r1 = lane + 32;  // stage-A rows
        const float4 id0 = g_idat[h][i0 + r0];
        const float4 id1 = g_idat[h][i0 + r1];
        const float th0 = -id0.x, A10 = id0.y, A20 = id0.z;
        const float th1 = -id1.x, A11 = id1.y, A21 = id1.z;
        float z0 = 0.f, z1 = 0.f;

        const uint32_t aOff = (uint32_t)((mgw * 32 + (lane & 15)) * 144 + (lane >> 4) * 16);
        const uint32_t bO = (uint32_t)((lane & 15) * 144 + (lane >> 4) * 16 + ngw * 64);

        float d[2][4][4] = {};

        // stage A: 16-j strip of fp16 W for rows lane and lane+32
        auto stageA = [&](int slotIdx, int wsel, unsigned w0, unsigned w1) {
            const char* jb = smem + SM_V + slotIdx * VCH + 9216 + q * 64;
            uint32_t vv0[8], vv1[8];
            #pragma unroll
            for (int u = 0; u < 4; u++) {
                float4 f0 = *(const float4*)(jb + u * 16);          // dst
                float4 f1 = *(const float4*)(jb + 256 + u * 16);    // e1
                float4 f2 = *(const float4*)(jb + 512 + u * 16);    // e2
                // row r0
                float a0 = (f0.x >= th0) ? A10 * f1.x : A20 * f2.x;
                float a1 = (f0.y >= th0) ? A10 * f1.y : A20 * f2.y;
                float a2 = (f0.z >= th0) ? A10 * f1.z : A20 * f2.z;
                float a3 = (f0.w >= th0) ? A10 * f1.w : A20 * f2.w;
                a0 = ((w0 >> (4 * u + 0)) & 1u) ? a0 : 0.f;
                a1 = ((w0 >> (4 * u + 1)) & 1u) ? a1 : 0.f;
                a2 = ((w0 >> (4 * u + 2)) & 1u) ? a2 : 0.f;
                a3 = ((w0 >> (4 * u + 3)) & 1u) ? a3 : 0.f;
                z0 += (a0 + a1) + (a2 + a3);
                __half2 p0 = __floats2half2_rn(a0, a1);
                __half2 p1 = __floats2half2_rn(a2, a3);
                vv0[2 * u] = *(uint32_t*)&p0; vv0[2 * u + 1] = *(uint32_t*)&p1;
                // row r1
                float b0 = (f0.x >= th1) ? A11 * f1.x : A21 * f2.x;
                float b1 = (f0.y >= th1) ? A11 * f1.y : A21 * f2.y;
                float b2 = (f0.z >= th1) ? A11 * f1.z : A21 * f2.z;
                float b3 = (f0.w >= th1) ? A11 * f1.w : A21 * f2.w;
                b0 = ((w1 >> (4 * u + 0)) & 1u) ? b0 : 0.f;
                b1 = ((w1 >> (4 * u + 1)) & 1u) ? b1 : 0.f;
                b2 = ((w1 >> (4 * u + 2)) & 1u) ? b2 : 0.f;
                b3 = ((w1 >> (4 * u + 3)) & 1u) ? b3 : 0.f;
                z1 += (b0 + b1) + (b2 + b3);
                __half2 p2 = __floats2half2_rn(b0, b1);
                __half2 p3 = __floats2half2_rn(b2, b3);
                vv1[2 * u] = *(uint32_t*)&p2; vv1[2 * u + 1] = *(uint32_t*)&p3;
            }
            char* w_ = smem + SM_W + wsel * 9216;
            char* pr0 = w_ + r0 * 144 + q * 32;
            char* pr1 = w_ + r1 * 144 + q * 32;
            *(uint4*)(pr0)      = make_uint4(vv0[0], vv0[1], vv0[2], vv0[3]);
            *(uint4*)(pr0 + 16) = make_uint4(vv0[4], vv0[5], vv0[6], vv0[7]);
            *(uint4*)(pr1)      = make_uint4(vv1[0], vv1[1], vv1[2], vv1[3]);
            *(uint4*)(pr1 + 16) = make_uint4(vv1[4], vv1[5], vv1[6], vv1[7]);
        };

        // prologue: chunk 0
        unsigned wc0 = g_adjT[q >> 1][i0 + r0] >> ((q & 1) * 16);
        unsigned wc1 = g_adjT[q >> 1][i0 + r1] >> ((q & 1) * 16);
        MBAR_WAIT(vfull + 0, 0);
        stageA(0, 0, wc0, wc1);
        BAR_SYNC(1, 128);

        int wsel = 0, slot = 0, cph = 0;
        #pragma unroll 1
        for (int m = 0; m < 64; m++) {
            // prefetch next adjacency words (hidden under MMA)
            unsigned wn0 = 0, wn1 = 0;
            if (m < 63) {
                wn0 = g_adjT[(m + 1) * 2 + (q >> 1)][i0 + r0] >> ((q & 1) * 16);
                wn1 = g_adjT[(m + 1) * 2 + (q >> 1)][i0 + r1] >> ((q & 1) * 16);
            }
            const uint32_t vb = sb + SM_V + slot * VCH;
            const uint32_t aW = sb + SM_W + wsel * 9216 + aOff;
            #pragma unroll
            for (int ks = 0; ks < 4; ks++) {
                uint32_t af[2][4];
                LDSM_X4(af[0], aW + ks * 32);
                LDSM_X4(af[1], aW + 2304 + ks * 32);
                const uint32_t kb = vb + (uint32_t)ks * 2304;
                uint32_t bfA[4], bfB[4];
                LDSM_X4T(bfA, kb + bO);
                LDSM_X4T(bfB, kb + bO + 32);
                MMA(d[0][0], af[0], bfA[0], bfA[1]); MMA(d[0][1], af[0], bfA[2], bfA[3]);
                MMA(d[0][2], af[0], bfB[0], bfB[1]); MMA(d[0][3], af[0], bfB[2], bfB[3]);
                MMA(d[1][0], af[1], bfA[0], bfA[1]); MMA(d[1][1], af[1], bfA[2], bfA[3]);
                MMA(d[1][2], af[1], bfB[0], bfB[1]); MMA(d[1][3], af[1], bfB[2], bfB[3]);
            }
            if (lane == 0) MBAR_ARRIVE(vfree + slot * 8);
            if (m < 63) {
                if (++slot == 3) { slot = 0; cph ^= 1; }
                MBAR_WAIT(vfull + slot * 8, cph);    // tile m+1 present
                stageA(slot, wsel ^ 1, wn0, wn1);
                wsel ^= 1;
                BAR_SYNC(1, 128);                    // W ready for next chunk
            }
        }

        // Z reduction across the 4 q-warps
        atomicAdd(&zs[r0], z0);
        atomicAdd(&zs[r1], z1);

        __syncthreads();
        // epilogue: warp owns rows mgw*32..+31, cols ngw*32..+31
        #pragma unroll
        for (int mt = 0; mt < 2; mt++) {
            int rlo = mgw * 32 + mt * 16 + (lane >> 2);
            int rhi = rlo + 8;
            float zlo = 1.0f / zs[rlo];
            float zhi = 1.0f / zs[rhi];
            #pragma unroll
            for (int nt = 0; nt < 4; nt++) {
                int col = h * OF + ngw * 32 + nt * 8 + (lane & 3) * 2;
                float* dd = d[mt][nt];
                float2 plo = make_float2(dd[0] * zlo, dd[1] * zlo);
                float2 phi = make_float2(dd[2] * zhi, dd[3] * zhi);
                *(float2*)(out + (size_t)(i0 + rlo) * (NH * OF) + col) = plo;
                *(float2*)(out + (size_t)(i0 + rhi) * (NH * OF) + col) = phi;
            }
        }
        return;
    }
    __syncthreads();   // TMA warp joins the epilogue barrier
}

// ---------------------------------------------------------------------------
extern "C" void kernel_launch(void* const* d_in, const int* in_sizes, int n_in,
                              void* d_out, int out_size) {
    const float* x   = (const float*)d_in[0];  // [4096, 256]
    const float* W   = (const float*)d_in[1];  // [4, 256, 64]
    const float* a   = (const float*)d_in[2];  // [4, 128]
    const int*   adj = (const int*)d_in[3];    // [4096, 4096]
    float* out = (float*)d_out;                // [4096, 256]
    (void)in_sizes; (void)n_in; (void)out_size;

    cudaFuncSetAttribute(k_main, cudaFuncAttributeMaxDynamicSharedMemorySize, SM_TOT);

    k_bitpack<<<(NN * NN / 16) / 256, 256>>>(adj);
    k_xtv<<<dim3(NN / 64, NH), 256>>>(x, W, a);
    k_main<<<dim3(NN / 64, NH), 160, SM_TOT>>>(out);
}

// round 12
// speedup vs baseline: 3.7315x; 1.0043x over previous
#include <cuda_runtime.h>
#include <cuda_fp16.h>
#include <cstdint>

#define NN 4096
#define INF 256
#define OF 64
#define NH 4

// ---------------------------------------------------------------------------
// Scratch globals
// ---------------------------------------------------------------------------
__device__ float4   g_idat[NH][NN];        // {src, exp(src), exp(0.2*src), 0}
__device__ unsigned g_adjT[NN / 32][NN];   // adjacency bits [wordcol][row]
// xt tiles: per (h,chunk): fp16 seg [64 k][64 n] (rows 144B) + 1KB tail:
//   [9216,9472) dst f32[64]   [9472,9728) e1 f32[64]   [9728,9984) e2 f32[64]
#define SEGB 9216
#define VCH  10240
__device__ __align__(16) char g_Vt[NH * 64 * VCH];

// ---------------------------------------------------------------------------
// PTX helpers (family-generic: no tcgen05 on compute_103 virtual target)
// ---------------------------------------------------------------------------
__device__ __forceinline__ uint32_t smem_u32(const void* p) {
    uint32_t a;
    asm("{ .reg .u64 t; cvta.to.shared.u64 t, %1; cvt.u32.u64 %0, t; }" : "=r"(a) : "l"(p));
    return a;
}
#define MBAR_INIT(a, n) asm volatile("mbarrier.init.shared.b64 [%0], %1;" :: "r"(a), "r"(n) : "memory")
#define MBAR_WAIT(a, ph) do {                                                            \
    uint32_t _m = (a), _p = (ph), _d;                                                    \
    asm volatile("{ .reg .pred p; mbarrier.try_wait.parity.acquire.cta.shared::cta.b64 " \
                 "p, [%1], %2; selp.b32 %0, 1, 0, p; }" : "=r"(_d) : "r"(_m), "r"(_p) : "memory"); \
    if (!_d) {                                                                           \
        asm volatile("{ .reg .pred P1; WL_%=: mbarrier.try_wait.parity.acquire.cta.shared::cta.b64 " \
                     "P1, [%0], %1, 0x989680; @P1 bra.uni WD_%=; bra.uni WL_%=; WD_%=: }" \
                     :: "r"(_m), "r"(_p) : "memory");                                    \
    }                                                                                    \
} while (0)
#define MBAR_ARRIVE(a) asm volatile("mbarrier.arrive.shared.b64 _, [%0];" :: "r"(a) : "memory")

#define LDSM_X4(r, a)                                                         \
    asm volatile("ldmatrix.sync.aligned.m8n8.x4.shared.b16 {%0,%1,%2,%3}, [%4];" \
        : "=r"((r)[0]), "=r"((r)[1]), "=r"((r)[2]), "=r"((r)[3]) : "r"(a))
#define LDSM_X4T(r, a)                                                        \
    asm volatile("ldmatrix.sync.aligned.m8n8.x4.trans.shared.b16 {%0,%1,%2,%3}, [%4];" \
        : "=r"((r)[0]), "=r"((r)[1]), "=r"((r)[2]), "=r"((r)[3]) : "r"(a))

#define MMA(d, a, b0_, b1_)                                                   \
    asm volatile("mma.sync.aligned.m16n8k16.row.col.f32.f16.f16.f32 "         \
        "{%0,%1,%2,%3},{%4,%5,%6,%7},{%8,%9},{%0,%1,%2,%3};"                  \
        : "+f"((d)[0]), "+f"((d)[1]), "+f"((d)[2]), "+f"((d)[3])              \
        : "r"((a)[0]), "r"((a)[1]), "r"((a)[2]), "r"((a)[3]), "r"(b0_), "r"(b1_))

// ---------------------------------------------------------------------------
// Kernel 1: adjacency bitpack (transposed), 16 elements/thread (measured best)
// ---------------------------------------------------------------------------
__global__ __launch_bounds__(256) void k_bitpack(const int* __restrict__ adj) {
    size_t tid = (size_t)blockIdx.x * 256 + threadIdx.x;
    int lane = threadIdx.x & 31;
    size_t base = tid * 16;
    int row = (int)(base >> 12), col = (int)(base & 4095);
    unsigned bits = 0;
    #pragma unroll
    for (int e = 0; e < 4; e++) {
        int4 v = *(const int4*)(adj + (size_t)row * NN + col + e * 4);
        bits |= ((unsigned)(v.x > 0) << (e * 4)) | ((unsigned)(v.y > 0) << (e * 4 + 1)) |
                ((unsigned)(v.z > 0) << (e * 4 + 2)) | ((unsigned)(v.w > 0) << (e * 4 + 3));
    }
    unsigned val = bits << (((unsigned)(col >> 4) & 1u) * 16u);
    val |= __shfl_xor_sync(0xffffffffu, val, 1);
    if ((lane & 1) == 0) g_adjT[col >> 5][row] = val;
}

// ---------------------------------------------------------------------------
// Kernel 2: xt GEMM + per-row scalars + fp16 xt-tile build (j-data in tail).
// ---------------------------------------------------------------------------
__global__ __launch_bounds__(256) void k_xtv(const float* __restrict__ x,
                                             const float* __restrict__ W,
                                             const float* __restrict__ a) {
    __shared__ float sx[16][68];
    __shared__ float sw[16][64];
    __shared__ float sxt[64][68];
    const int h = blockIdx.y, n0 = blockIdx.x * 64, t = threadIdx.x;
    const int tx = t & 15, ty = t >> 4;
    const float* Wh = W + h * INF * OF;

    float acc[4][4] = {};
    for (int k0 = 0; k0 < INF; k0 += 16) {
        const int n = t >> 2, kq = (t & 3) * 4;
        float4 xv = *(const float4*)(x + (n0 + n) * INF + k0 + kq);
        const int kk = t & 15, f4 = t >> 4;
        float4 wv = *(const float4*)(Wh + (kk + k0) * OF + f4 * 4);
        __syncthreads();
        sx[kq + 0][n] = xv.x; sx[kq + 1][n] = xv.y;
        sx[kq + 2][n] = xv.z; sx[kq + 3][n] = xv.w;
        *(float4*)&sw[kk][f4 * 4] = wv;
        __syncthreads();
        #pragma unroll
        for (int k = 0; k < 16; k++) {
            float4 av = *(float4*)&sx[k][ty * 4];
            float4 bv = *(float4*)&sw[k][tx * 4];
            acc[0][0] += av.x * bv.x; acc[0][1] += av.x * bv.y; acc[0][2] += av.x * bv.z; acc[0][3] += av.x * bv.w;
            acc[1][0] += av.y * bv.x; acc[1][1] += av.y * bv.y; acc[1][2] += av.y * bv.z; acc[1][3] += av.y * bv.w;
            acc[2][0] += av.z * bv.x; acc[2][1] += av.z * bv.y; acc[2][2] += av.z * bv.z; acc[2][3] += av.z * bv.w;
            acc[3][0] += av.w * bv.x; acc[3][1] += av.w * bv.y; acc[3][2] += av.w * bv.z; acc[3][3] += av.w * bv.w;
        }
    }
    __syncthreads();
    #pragma unroll
    for (int r = 0; r < 4; r++)
        *(float4*)&sxt[ty * 4 + r][tx * 4] = make_float4(acc[r][0], acc[r][1], acc[r][2], acc[r][3]);
    __syncthreads();

    char* tb = g_Vt + (size_t)(h * 64 + blockIdx.x) * VCH;

    {
        const int row = t >> 2, qq = t & 3;
        const float* ah = a + h * 2 * OF;
        float s = 0.f, d = 0.f;
        #pragma unroll
        for (int ff = 0; ff < 16; ff++) {
            int f = qq * 16 + ff;
            float v = sxt[row][f];
            s += v * ah[f];
            d += v * ah[OF + f];
        }
        s += __shfl_xor_sync(0xffffffffu, s, 1); s += __shfl_xor_sync(0xffffffffu, s, 2);
        d += __shfl_xor_sync(0xffffffffu, d, 1); d += __shfl_xor_sync(0xffffffffu, d, 2);
        if (qq == 0) {
            g_idat[h][n0 + row] = make_float4(s, expf(s), expf(0.2f * s), 0.f);
            *(float*)(tb + 9216 + row * 4) = d;
            *(float*)(tb + 9472 + row * 4) = expf(d);
            *(float*)(tb + 9728 + row * 4) = expf(0.2f * d);
        }
    }
    __syncthreads();

    for (int idx = t; idx < 64 * 32; idx += 256) {
        int k = idx >> 5, u = idx & 31;
        int c0 = u * 2;
        __half2 hp = __floats2half2_rn(sxt[k][c0], sxt[k][c0 + 1]);
        *(uint32_t*)(tb + k * 144 + u * 4) = *(uint32_t*)&hp;
    }
}

// ---------------------------------------------------------------------------
// Kernel 3 (main): producer/consumer warp specialization.
// 288 threads, 2 CTAs/SM: warps 0-3 MMA consumers (mg2 x ng2), warps 4-7
// stage-A producers (j-quarter each), warp 8 TMA. W double-buffered with
// wfull/wfree mbarriers; V 3-deep ring with vfull/vfree. No named barriers —
// producer(m+1) overlaps consumer(m) on every SMSP.
// ---------------------------------------------------------------------------
#define SM_V   0                      // 3 x 10240 = 30720
#define SM_W   30720                  // 2 x 9216 = 18432
#define SM_Z   49152                  // 64 floats = 256B
#define SM_MB  49408                  // wfull[2] wfree[2] vfull[3] vfree[3]
#define SM_TOT 49536

__global__ __launch_bounds__(288, 2) void k_main(float* __restrict__ out) {
    extern __shared__ char smem[];
    const uint32_t sb = smem_u32(smem);
    const int h = blockIdx.y, i0 = blockIdx.x * 64;
    const int t = threadIdx.x, wid = t >> 5, lane = t & 31;
    const uint32_t wfull = sb + SM_MB;        // +0, +8
    const uint32_t wfree = sb + SM_MB + 16;   // +0, +8
    const uint32_t vfull = sb + SM_MB + 32;   // +0, +8, +16
    const uint32_t vfreeB = sb + SM_MB + 56;  // +0, +8, +16
    float* zs = (float*)(smem + SM_Z);

    if (t == 0) {
        MBAR_INIT(wfull + 0, 128); MBAR_INIT(wfull + 8, 128);
        MBAR_INIT(wfree + 0, 128); MBAR_INIT(wfree + 8, 128);
        #pragma unroll
        for (int s = 0; s < 3; s++) {
            MBAR_INIT(vfull + s * 8, 1);
            MBAR_INIT(vfreeB + s * 8, 256);
        }
    }
    if (t < 64) zs[t] = 0.f;
    __syncthreads();

    if (wid == 8) {
        // ----------------------------- TMA warp -----------------------------
        if (lane == 0) {
            int slot = 0;
            #pragma unroll 1
            for (int m = 0; m < 64; m++) {
                if (m >= 3) MBAR_WAIT(vfreeB + slot * 8, ((m - 3) / 3) & 1);
                asm volatile("mbarrier.arrive.expect_tx.shared.b64 _, [%0], %1;"
                             :: "r"(vfull + slot * 8), "r"((uint32_t)VCH) : "memory");
                const char* src = g_Vt + (size_t)(h * 64 + m) * VCH;
                uint64_t sg; asm("cvta.to.global.u64 %0, %1;" : "=l"(sg) : "l"(src));
                asm volatile("cp.async.bulk.shared::cluster.global.mbarrier::complete_tx::bytes "
                             "[%0], [%1], %2, [%3];"
                             :: "r"(sb + SM_V + slot * VCH), "l"(sg), "r"((uint32_t)VCH),
                                "r"(vfull + slot * 8) : "memory");
                if (++slot == 3) slot = 0;
            }
        }
    } else if (wid >= 4) {
        // ------------------------- 4 producer warps -------------------------
        const int q = wid - 4;                // j-quarter
        const int r0 = lane, r1 = lane + 32;
        const float4 id0 = g_idat[h][i0 + r0];
        const float4 id1 = g_idat[h][i0 + r1];
        const float th0 = -id0.x, A10 = id0.y, A20 = id0.z;
        const float th1 = -id1.x, A11 = id1.y, A21 = id1.z;
        float z0 = 0.f, z1 = 0.f;

        unsigned wc0 = g_adjT[q >> 1][i0 + r0] >> ((q & 1) * 16);
        unsigned wc1 = g_adjT[q >> 1][i0 + r1] >> ((q & 1) * 16);

        int vslot = 0, vph = 0;
        #pragma unroll 1
        for (int m = 0; m < 64; m++) {
            // prefetch next adjacency words (latency hidden under stage A)
            unsigned wn0 = 0, wn1 = 0;
            if (m < 63) {
                wn0 = g_adjT[(m + 1) * 2 + (q >> 1)][i0 + r0] >> ((q & 1) * 16);
                wn1 = g_adjT[(m + 1) * 2 + (q >> 1)][i0 + r1] >> ((q & 1) * 16);
            }
            MBAR_WAIT(vfull + vslot * 8, vph);                       // tile m tail
            if (m >= 2) MBAR_WAIT(wfree + (m & 1) * 8, ((m - 2) >> 1) & 1);

            const char* jb = smem + SM_V + vslot * VCH + 9216 + q * 64;
            uint32_t vv0[8], vv1[8];
            #pragma unroll
            for (int u = 0; u < 4; u++) {
                float4 f0 = *(const float4*)(jb + u * 16);          // dst
                float4 f1 = *(const float4*)(jb + 256 + u * 16);    // e1
                float4 f2 = *(const float4*)(jb + 512 + u * 16);    // e2
                float a0 = (f0.x >= th0) ? A10 * f1.x : A20 * f2.x;
                float a1 = (f0.y >= th0) ? A10 * f1.y : A20 * f2.y;
                float a2 = (f0.z >= th0) ? A10 * f1.z : A20 * f2.z;
                float a3 = (f0.w >= th0) ? A10 * f1.w : A20 * f2.w;
                a0 = ((wc0 >> (4 * u + 0)) & 1u) ? a0 : 0.f;
                a1 = ((wc0 >> (4 * u + 1)) & 1u) ? a1 : 0.f;
                a2 = ((wc0 >> (4 * u + 2)) & 1u) ? a2 : 0.f;
                a3 = ((wc0 >> (4 * u + 3)) & 1u) ? a3 : 0.f;
                z0 += (a0 + a1) + (a2 + a3);
                __half2 p0 = __floats2half2_rn(a0, a1);
                __half2 p1 = __floats2half2_rn(a2, a3);
                vv0[2 * u] = *(uint32_t*)&p0; vv0[2 * u + 1] = *(uint32_t*)&p1;
                float b0 = (f0.x >= th1) ? A11 * f1.x : A21 * f2.x;
                float b1 = (f0.y >= th1) ? A11 * f1.y : A21 * f2.y;
                float b2 = (f0.z >= th1) ? A11 * f1.z : A21 * f2.z;
                float b3 = (f0.w >= th1) ? A11 * f1.w : A21 * f2.w;
                b0 = ((wc1 >> (4 * u + 0)) & 1u) ? b0 : 0.f;
                b1 = ((wc1 >> (4 * u + 1)) & 1u) ? b1 : 0.f;
                b2 = ((wc1 >> (4 * u + 2)) & 1u) ? b2 : 0.f;
                b3 = ((wc1 >> (4 * u + 3)) & 1u) ? b3 : 0.f;
                z1 += (b0 + b1) + (b2 + b3);
                __half2 p2 = __floats2half2_rn(b0, b1);
                __half2 p3 = __floats2half2_rn(b2, b3);
                vv1[2 * u] = *(uint32_t*)&p2; vv1[2 * u + 1] = *(uint32_t*)&p3;
            }
            char* w_ = smem + SM_W + (m & 1) * 9216;
            char* pr0 = w_ + r0 * 144 + q * 32;
            char* pr1 = w_ + r1 * 144 + q * 32;
            *(uint4*)(pr0)      = make_uint4(vv0[0], vv0[1], vv0[2], vv0[3]);
            *(uint4*)(pr0 + 16) = make_uint4(vv0[4], vv0[5], vv0[6], vv0[7]);
            *(uint4*)(pr1)      = make_uint4(vv1[0], vv1[1], vv1[2], vv1[3]);
            *(uint4*)(pr1 + 16) = make_uint4(vv1[4], vv1[5], vv1[6], vv1[7]);

            MBAR_ARRIVE(wfull + (m & 1) * 8);     // all 128 producer threads
            MBAR_ARRIVE(vfreeB + vslot * 8);      // producer release of tile m
            wc0 = wn0; wc1 = wn1;
            if (++vslot == 3) { vslot = 0; vph ^= 1; }
        }
        atomicAdd(&zs[r0], z0);
        atomicAdd(&zs[r1], z1);
    } else {
        // ------------------------- 4 consumer warps -------------------------
        const int mgw = wid >> 1, ngw = wid & 1;
        const uint32_t aOff = (uint32_t)((mgw * 32 + (lane & 15)) * 144 + (lane >> 4) * 16);
        const uint32_t bO = (uint32_t)((lane & 15) * 144 + (lane >> 4) * 16 + ngw * 64);
        float d[2][4][4] = {};

        int vslot = 0, vph = 0;
        #pragma unroll 1
        for (int m = 0; m < 64; m++) {
            MBAR_WAIT(wfull + (m & 1) * 8, (m >> 1) & 1);
            MBAR_WAIT(vfull + vslot * 8, vph);
            const uint32_t vb = sb + SM_V + vslot * VCH;
            const uint32_t aW = sb + SM_W + (m & 1) * 9216 + aOff;
            #pragma unroll
            for (int ks = 0; ks < 4; ks++) {
                uint32_t af[2][4];
                LDSM_X4(af[0], aW + ks * 32);
                LDSM_X4(af[1], aW + 2304 + ks * 32);
                const uint32_t kb = vb + (uint32_t)ks * 2304;
                uint32_t bfA[4], bfB[4];
                LDSM_X4T(bfA, kb + bO);
                LDSM_X4T(bfB, kb + bO + 32);
                MMA(d[0][0], af[0], bfA[0], bfA[1]); MMA(d[0][1], af[0], bfA[2], bfA[3]);
                MMA(d[0][2], af[0], bfB[0], bfB[1]); MMA(d[0][3], af[0], bfB[2], bfB[3]);
                MMA(d[1][0], af[1], bfA[0], bfA[1]); MMA(d[1][1], af[1], bfA[2], bfA[3]);
                MMA(d[1][2], af[1], bfB[0], bfB[1]); MMA(d[1][3], af[1], bfB[2], bfB[3]);
            }
            MBAR_ARRIVE(wfree + (m & 1) * 8);     // all 128 consumer threads
            MBAR_ARRIVE(vfreeB + vslot * 8);      // consumer release of tile m
            if (++vslot == 3) { vslot = 0; vph ^= 1; }
        }

        __syncthreads();   // join with producers' zs atomics
        #pragma unroll
        for (int mt = 0; mt < 2; mt++) {
            int rlo = mgw * 32 + mt * 16 + (lane >> 2);
            int rhi = rlo + 8;
            float zlo = 1.0f / zs[rlo];
            float zhi = 1.0f / zs[rhi];
            #pragma unroll
            for (int nt = 0; nt < 4; nt++) {
                int col = h * OF + ngw * 32 + nt * 8 + (lane & 3) * 2;
                float* dd = d[mt][nt];
                float2 plo = make_float2(dd[0] * zlo, dd[1] * zlo);
                float2 phi = make_float2(dd[2] * zhi, dd[3] * zhi);
                *(float2*)(out + (size_t)(i0 + rlo) * (NH * OF) + col) = plo;
                *(float2*)(out + (size_t)(i0 + rhi) * (NH * OF) + col) = phi;
            }
        }
        return;
    }
    __syncthreads();   // producers + TMA warp join the epilogue barrier
}

// ---------------------------------------------------------------------------
extern "C" void kernel_launch(void* const* d_in, const int* in_sizes, int n_in,
                              void* d_out, int out_size) {
    const float* x   = (const float*)d_in[0];  // [4096, 256]
    const float* W   = (const float*)d_in[1];  // [4, 256, 64]
    const float* a   = (const float*)d_in[2];  // [4, 128]
    const int*   adj = (const int*)d_in[3];    // [4096, 4096]
    float* out = (float*)d_out;                // [4096, 256]
    (void)in_sizes; (void)n_in; (void)out_size;

    cudaFuncSetAttribute(k_main, cudaFuncAttributeMaxDynamicSharedMemorySize, SM_TOT);

    k_bitpack<<<(NN * NN / 16) / 256, 256>>>(adj);
    k_xtv<<<dim3(NN / 64, NH), 256>>>(x, W, a);
    k_main<<<dim3(NN / 64, NH), 288, SM_TOT>>>(out);
}